// round 6
// baseline (speedup 1.0000x reference)
#include <cuda_runtime.h>
#include <cstdint>
#include <cstddef>

// ---------------------------------------------------------------------------
// ViT-Base encoder, fp32 SIMT baseline (Round 1).
// B=8, N=1024 tokens, D=768, 8 layers, 12 heads x 64, MLP=3072.
// Residual stream lives in d_out; scratch in __device__ globals.
// ---------------------------------------------------------------------------

#define BB    8
#define NTOK  1024
#define DD    768
#define DEPTH 8
#define HEADS 12
#define DH    64
#define MLPD  3072
#define BN_   (BB * NTOK)          // 8192 rows
#define QKV3  (3 * DD)             // 2304

// ----------------------------- scratch -------------------------------------
__device__ float g_y[(size_t)BN_ * DD];
__device__ float g_qkv[(size_t)BN_ * QKV3];
__device__ float g_scores[(size_t)BB * HEADS * NTOK * NTOK];
__device__ float g_o[(size_t)BN_ * DD];
__device__ float g_mlp[(size_t)BN_ * MLPD];

// ------------------------- patch embed + pos -------------------------------
__global__ void patch_embed_kernel(const float* __restrict__ x,
                                   const float* __restrict__ wconv,
                                   const float* __restrict__ bconv,
                                   const float* __restrict__ pos,
                                   float* __restrict__ h) {
    int bn = blockIdx.x;                 // 0..8191
    int b = bn >> 10, n = bn & 1023;
    int py = n >> 5, px = n & 31;        // 32 patches per image row
    __shared__ float patch[192];
    int tid = threadIdx.x;               // 256 threads
    if (tid < 192) {
        int c = tid / 64;
        int rem = tid - c * 64;
        int i = rem >> 3, j = rem & 7;
        patch[tid] = x[(((size_t)(b * 3 + c) * 256) + (size_t)(py * 8 + i)) * 256
                       + (size_t)(px * 8 + j)];
    }
    __syncthreads();
    for (int d = tid; d < DD; d += 256) {
        const float* wr = wconv + (size_t)d * 192;
        float s = 0.f;
#pragma unroll
        for (int t = 0; t < 192; ++t) s += patch[t] * wr[t];
        h[(size_t)bn * DD + d] = s + bconv[d] + pos[(size_t)n * DD + d];
    }
}

// ------------------------------ layernorm ----------------------------------
__global__ void layernorm_kernel(const float* __restrict__ h,
                                 const float* __restrict__ w,
                                 const float* __restrict__ bsh,
                                 float* __restrict__ y) {
    int row = blockIdx.x;
    const float* hr = h + (size_t)row * DD;
    int tid = threadIdx.x;               // 256
    float v0 = hr[tid], v1 = hr[tid + 256], v2 = hr[tid + 512];
    float s = v0 + v1 + v2;
    float sq = v0 * v0 + v1 * v1 + v2 * v2;
#pragma unroll
    for (int o = 16; o; o >>= 1) {
        s += __shfl_xor_sync(0xffffffffu, s, o);
        sq += __shfl_xor_sync(0xffffffffu, sq, o);
    }
    __shared__ float rs[8], rq[8];
    __shared__ float mean_s, rstd_s;
    int warp = tid >> 5, lane = tid & 31;
    if (lane == 0) { rs[warp] = s; rq[warp] = sq; }
    __syncthreads();
    if (tid == 0) {
        float S = 0.f, SQ = 0.f;
#pragma unroll
        for (int i = 0; i < 8; ++i) { S += rs[i]; SQ += rq[i]; }
        float m = S * (1.0f / DD);
        float var = SQ * (1.0f / DD) - m * m;
        mean_s = m;
        rstd_s = rsqrtf(var + 1e-5f);
    }
    __syncthreads();
    float m = mean_s, r = rstd_s;
    float* yr = y + (size_t)row * DD;
    yr[tid]       = (v0 - m) * r * w[tid]       + bsh[tid];
    yr[tid + 256] = (v1 - m) * r * w[tid + 256] + bsh[tid + 256];
    yr[tid + 512] = (v2 - m) * r * w[tid + 512] + bsh[tid + 512];
}

// ------------------------------ generic GEMM -------------------------------
// C[M,N] = A[M,K] @ B[K,N]   (row-major; M%128==0, N%128==0, K%16==0)
#define TBM 128
#define TBN 128
#define TBK 16

#define EPI_STORE     0
#define EPI_BIAS_RES  2
#define EPI_BIAS_GELU 3

template <int EPI>
__global__ void __launch_bounds__(256)
gemm_kernel(const float* __restrict__ A, const float* __restrict__ Bm,
            float* __restrict__ C, const float* __restrict__ bias,
            const float* __restrict__ res, int M, int Np, int K) {
    __shared__ float As[TBK][TBM + 4];
    __shared__ float Bs[TBK][TBN + 4];
    int tid = threadIdx.x;
    int tx = tid & 15, ty = tid >> 4;
    int m0 = blockIdx.y * TBM, n0 = blockIdx.x * TBN;

    float acc[8][8];
#pragma unroll
    for (int i = 0; i < 8; ++i)
#pragma unroll
        for (int j = 0; j < 8; ++j) acc[i][j] = 0.f;

    int ra = tid >> 2;               // 0..63
    int ca = (tid & 3) * 4;          // 0,4,8,12
    int rb = tid >> 5;               // 0..7
    int cb = (tid & 31) * 4;         // 0..124

    int nk = K / TBK;
    for (int kt = 0; kt < nk; ++kt) {
#pragma unroll
        for (int p = 0; p < 2; ++p) {
            float4 a = *(const float4*)(A + (size_t)(m0 + ra + p * 64) * K + kt * TBK + ca);
            As[ca + 0][ra + p * 64] = a.x;
            As[ca + 1][ra + p * 64] = a.y;
            As[ca + 2][ra + p * 64] = a.z;
            As[ca + 3][ra + p * 64] = a.w;
        }
#pragma unroll
        for (int p = 0; p < 2; ++p) {
            float4 b = *(const float4*)(Bm + (size_t)(kt * TBK + rb + p * 8) * Np + n0 + cb);
            *(float4*)&Bs[rb + p * 8][cb] = b;
        }
        __syncthreads();
#pragma unroll
        for (int k = 0; k < TBK; ++k) {
            float ar[8], br[8];
            *(float4*)&ar[0] = *(const float4*)&As[k][ty * 8];
            *(float4*)&ar[4] = *(const float4*)&As[k][ty * 8 + 4];
            *(float4*)&br[0] = *(const float4*)&Bs[k][tx * 8];
            *(float4*)&br[4] = *(const float4*)&Bs[k][tx * 8 + 4];
#pragma unroll
            for (int i = 0; i < 8; ++i)
#pragma unroll
                for (int j = 0; j < 8; ++j) acc[i][j] += ar[i] * br[j];
        }
        __syncthreads();
    }

#pragma unroll
    for (int i = 0; i < 8; ++i) {
        int m = m0 + ty * 8 + i;
#pragma unroll
        for (int j = 0; j < 8; ++j) {
            int n = n0 + tx * 8 + j;
            float v = acc[i][j];
            if (EPI == EPI_BIAS_RES) {
                v += bias[n];
                v += res[(size_t)m * Np + n];
            } else if (EPI == EPI_BIAS_GELU) {
                v += bias[n];
                v = 0.5f * v * (1.0f + erff(v * 0.70710678118654752f));
            }
            C[(size_t)m * Np + n] = v;
        }
    }
}

// ------------------------ attention: Q @ K^T * scale -----------------------
__global__ void __launch_bounds__(256)
attn_scores_kernel(const float* __restrict__ qkv) {
    int bh = blockIdx.z;
    int b = bh / HEADS, hd = bh - b * HEADS;
    const float* Q  = qkv + (size_t)b * NTOK * QKV3 + hd * DH;
    const float* Kp = qkv + (size_t)b * NTOK * QKV3 + DD + hd * DH;
    float* Cp = g_scores + (size_t)bh * NTOK * NTOK;

    int m0 = blockIdx.y * 64, n0 = blockIdx.x * 64;
    __shared__ float Qs[64][68];  // [k][m]
    __shared__ float Ks[64][68];  // [k][n]
    int tid = threadIdx.x;
    int r = tid >> 2;             // 0..63
    int c4 = (tid & 3) * 4;       // 0..12
#pragma unroll
    for (int p = 0; p < 4; ++p) {
        int kc = c4 + p * 16;
        float4 q = *(const float4*)(Q + (size_t)(m0 + r) * QKV3 + kc);
        Qs[kc + 0][r] = q.x; Qs[kc + 1][r] = q.y; Qs[kc + 2][r] = q.z; Qs[kc + 3][r] = q.w;
        float4 kk = *(const float4*)(Kp + (size_t)(n0 + r) * QKV3 + kc);
        Ks[kc + 0][r] = kk.x; Ks[kc + 1][r] = kk.y; Ks[kc + 2][r] = kk.z; Ks[kc + 3][r] = kk.w;
    }
    __syncthreads();

    int tx = tid & 15, ty = tid >> 4;
    float acc[4][4];
#pragma unroll
    for (int i = 0; i < 4; ++i)
#pragma unroll
        for (int j = 0; j < 4; ++j) acc[i][j] = 0.f;

#pragma unroll 8
    for (int k = 0; k < 64; ++k) {
        float ar[4], br[4];
        *(float4*)&ar[0] = *(const float4*)&Qs[k][ty * 4];
        *(float4*)&br[0] = *(const float4*)&Ks[k][tx * 4];
#pragma unroll
        for (int i = 0; i < 4; ++i)
#pragma unroll
            for (int j = 0; j < 4; ++j) acc[i][j] += ar[i] * br[j];
    }
    const float scale = 0.125f;   // DH^-0.5
#pragma unroll
    for (int i = 0; i < 4; ++i)
#pragma unroll
        for (int j = 0; j < 4; ++j)
            Cp[(size_t)(m0 + ty * 4 + i) * NTOK + n0 + tx * 4 + j] = acc[i][j] * scale;
}

// ------------------------------- softmax -----------------------------------
__global__ void softmax_kernel() {
    float* row = g_scores + (size_t)blockIdx.x * NTOK;
    int tid = threadIdx.x;   // 256
    float v[4];
#pragma unroll
    for (int i = 0; i < 4; ++i) v[i] = row[tid + 256 * i];
    float mx = fmaxf(fmaxf(v[0], v[1]), fmaxf(v[2], v[3]));
#pragma unroll
    for (int o = 16; o; o >>= 1) mx = fmaxf(mx, __shfl_xor_sync(0xffffffffu, mx, o));
    __shared__ float red[8];
    __shared__ float bmax, binv;
    int warp = tid >> 5, lane = tid & 31;
    if (lane == 0) red[warp] = mx;
    __syncthreads();
    if (tid == 0) {
        float m = red[0];
#pragma unroll
        for (int i = 1; i < 8; ++i) m = fmaxf(m, red[i]);
        bmax = m;
    }
    __syncthreads();
    mx = bmax;
    float sum = 0.f;
#pragma unroll
    for (int i = 0; i < 4; ++i) { v[i] = __expf(v[i] - mx); sum += v[i]; }
#pragma unroll
    for (int o = 16; o; o >>= 1) sum += __shfl_xor_sync(0xffffffffu, sum, o);
    if (lane == 0) red[warp] = sum;
    __syncthreads();
    if (tid == 0) {
        float S = 0.f;
#pragma unroll
        for (int i = 0; i < 8; ++i) S += red[i];
        binv = 1.0f / S;
    }
    __syncthreads();
    float inv = binv;
#pragma unroll
    for (int i = 0; i < 4; ++i) row[tid + 256 * i] = v[i] * inv;
}

// -------------------------- attention: P @ V -------------------------------
__global__ void __launch_bounds__(256)
attn_v_kernel(const float* __restrict__ qkv, float* __restrict__ o) {
    int bh = blockIdx.y;
    int b = bh / HEADS, hd = bh - b * HEADS;
    const float* Ap = g_scores + (size_t)bh * NTOK * NTOK;
    const float* Vp = qkv + (size_t)b * NTOK * QKV3 + 2 * DD + hd * DH;
    int m0 = blockIdx.x * 64;

    __shared__ float As2[64][68];  // [k][m]
    __shared__ float Vs[64][68];   // [k][d]
    int tid = threadIdx.x;
    int r = tid >> 2;
    int c4 = (tid & 3) * 4;
    int tx = tid & 15, ty = tid >> 4;

    float acc[4][4];
#pragma unroll
    for (int i = 0; i < 4; ++i)
#pragma unroll
        for (int j = 0; j < 4; ++j) acc[i][j] = 0.f;

    for (int kt = 0; kt < NTOK / 64; ++kt) {
#pragma unroll
        for (int p = 0; p < 4; ++p) {
            int kc = c4 + p * 16;
            float4 a = *(const float4*)(Ap + (size_t)(m0 + r) * NTOK + kt * 64 + kc);
            As2[kc + 0][r] = a.x; As2[kc + 1][r] = a.y; As2[kc + 2][r] = a.z; As2[kc + 3][r] = a.w;
            float4 vv = *(const float4*)(Vp + (size_t)(kt * 64 + r) * QKV3 + kc);
            *(float4*)&Vs[r][kc] = vv;
        }
        __syncthreads();
#pragma unroll 8
        for (int k = 0; k < 64; ++k) {
            float ar[4], br[4];
            *(float4*)&ar[0] = *(const float4*)&As2[k][ty * 4];
            *(float4*)&br[0] = *(const float4*)&Vs[k][tx * 4];
#pragma unroll
            for (int i = 0; i < 4; ++i)
#pragma unroll
                for (int j = 0; j < 4; ++j) acc[i][j] += ar[i] * br[j];
        }
        __syncthreads();
    }
#pragma unroll
    for (int i = 0; i < 4; ++i)
#pragma unroll
        for (int j = 0; j < 4; ++j)
            o[(size_t)(b * NTOK + m0 + ty * 4 + i) * DD + hd * DH + tx * 4 + j] = acc[i][j];
}

// ------------------------------- launcher ----------------------------------
extern "C" void kernel_launch(void* const* d_in, const int* in_sizes, int n_in,
                              void* d_out, int out_size) {
    const float* x       = (const float*)d_in[0];
    const float* w_conv  = (const float*)d_in[1];
    const float* b_conv  = (const float*)d_in[2];
    const float* pos_emb = (const float*)d_in[3];
    const float* ln1_w   = (const float*)d_in[4];
    const float* ln1_b   = (const float*)d_in[5];
    const float* qkv_w   = (const float*)d_in[6];
    const float* out_w   = (const float*)d_in[7];
    const float* out_b   = (const float*)d_in[8];
    const float* ln2_w   = (const float*)d_in[9];
    const float* ln2_b   = (const float*)d_in[10];
    const float* w1      = (const float*)d_in[11];
    const float* b1      = (const float*)d_in[12];
    const float* w2      = (const float*)d_in[13];
    const float* b2      = (const float*)d_in[14];

    float* h = (float*)d_out;   // residual stream lives in d_out

    float *yb, *qkvb, *ob, *mlpb;
    cudaGetSymbolAddress((void**)&yb,   g_y);
    cudaGetSymbolAddress((void**)&qkvb, g_qkv);
    cudaGetSymbolAddress((void**)&ob,   g_o);
    cudaGetSymbolAddress((void**)&mlpb, g_mlp);

    patch_embed_kernel<<<BN_, 256>>>(x, w_conv, b_conv, pos_emb, h);

    for (int L = 0; L < DEPTH; ++L) {
        // --- MHSA ---
        layernorm_kernel<<<BN_, 256>>>(h, ln1_w + L * DD, ln1_b + L * DD, yb);

        dim3 gq(QKV3 / TBN, BN_ / TBM);
        gemm_kernel<EPI_STORE><<<gq, 256>>>(yb, qkv_w + (size_t)L * DD * QKV3,
                                            qkvb, nullptr, nullptr, BN_, QKV3, DD);

        dim3 gs(NTOK / 64, NTOK / 64, BB * HEADS);
        attn_scores_kernel<<<gs, 256>>>(qkvb);

        softmax_kernel<<<BB * HEADS * NTOK, 256>>>();

        dim3 gv(NTOK / 64, BB * HEADS);
        attn_v_kernel<<<gv, 256>>>(qkvb, ob);

        dim3 gp(DD / TBN, BN_ / TBM);
        gemm_kernel<EPI_BIAS_RES><<<gp, 256>>>(ob, out_w + (size_t)L * DD * DD,
                                               h, out_b + L * DD, h, BN_, DD, DD);

        // --- FFN ---
        layernorm_kernel<<<BN_, 256>>>(h, ln2_w + L * DD, ln2_b + L * DD, yb);

        dim3 g1(MLPD / TBN, BN_ / TBM);
        gemm_kernel<EPI_BIAS_GELU><<<g1, 256>>>(yb, w1 + (size_t)L * DD * MLPD,
                                                mlpb, b1 + L * MLPD, nullptr, BN_, MLPD, DD);

        dim3 g2(DD / TBN, BN_ / TBM);
        gemm_kernel<EPI_BIAS_RES><<<g2, 256>>>(mlpb, w2 + (size_t)L * MLPD * DD,
                                               h, b2 + L * DD, h, BN_, DD, MLPD);
    }
    (void)in_sizes; (void)n_in; (void)out_size;
}

// round 8
// speedup vs baseline: 1.6242x; 1.6242x over previous
#include <cuda_runtime.h>
#include <cuda_bf16.h>
#include <cstdint>
#include <cstddef>

// ---------------------------------------------------------------------------
// ViT-Base encoder. Round 7: dense GEMMs on mma.sync bf16 (HMMA) with
// 3-term bf16 split for fp32 fidelity. cp.async double-buffered pipeline.
// (tcgen05 PTX is rejected by this harness's base-target compute_103 pass.)
// B=8, N=1024 tokens, D=768, 8 layers, 12 heads x 64, MLP=3072.
// ---------------------------------------------------------------------------

#define BB    8
#define NTOK  1024
#define DD    768
#define DEPTH 8
#define HEADS 12
#define DH    64
#define MLPD  3072
#define BN_   (BB * NTOK)          // 8192 rows
#define QKV3  (3 * DD)             // 2304

// ----------------------------- scratch -------------------------------------
__device__ float g_qkv[(size_t)BN_ * QKV3];
__device__ float g_scores[(size_t)BB * HEADS * NTOK * NTOK];

// activation bf16 hi/lo (GEMM A operands)
__device__ __nv_bfloat16 g_yh[(size_t)BN_ * DD];
__device__ __nv_bfloat16 g_yl[(size_t)BN_ * DD];
__device__ __nv_bfloat16 g_oh[(size_t)BN_ * DD];
__device__ __nv_bfloat16 g_ol[(size_t)BN_ * DD];
__device__ __nv_bfloat16 g_mh[(size_t)BN_ * MLPD];
__device__ __nv_bfloat16 g_ml[(size_t)BN_ * MLPD];

// transposed + bf16-split weights: Wt[n][k] = W[k][n]
__device__ __nv_bfloat16 g_wq_hi[(size_t)DEPTH * QKV3 * DD];
__device__ __nv_bfloat16 g_wq_lo[(size_t)DEPTH * QKV3 * DD];
__device__ __nv_bfloat16 g_wo_hi[(size_t)DEPTH * DD * DD];
__device__ __nv_bfloat16 g_wo_lo[(size_t)DEPTH * DD * DD];
__device__ __nv_bfloat16 g_w1_hi[(size_t)DEPTH * MLPD * DD];
__device__ __nv_bfloat16 g_w1_lo[(size_t)DEPTH * MLPD * DD];
__device__ __nv_bfloat16 g_w2_hi[(size_t)DEPTH * DD * MLPD];
__device__ __nv_bfloat16 g_w2_lo[(size_t)DEPTH * DD * MLPD];

// --------------------------- PTX helpers (base-target legal) ---------------
__device__ __forceinline__ uint32_t smem_u32(const void* p) {
    uint32_t a;
    asm("{ .reg .u64 t; cvta.to.shared.u64 t, %1; cvt.u32.u64 %0, t; }"
        : "=r"(a) : "l"(p));
    return a;
}

__device__ __forceinline__ void cp16(uint32_t s, const void* g) {
    asm volatile("cp.async.cg.shared.global [%0], [%1], 16;" :: "r"(s), "l"(g));
}
__device__ __forceinline__ void cp_commit() {
    asm volatile("cp.async.commit_group;" ::: "memory");
}
template <int N>
__device__ __forceinline__ void cp_wait() {
    asm volatile("cp.async.wait_group %0;" :: "n"(N) : "memory");
}

__device__ __forceinline__ void ldsm_x4(uint32_t* r, uint32_t addr) {
    asm volatile("ldmatrix.sync.aligned.m8n8.x4.shared.b16 {%0,%1,%2,%3}, [%4];"
                 : "=r"(r[0]), "=r"(r[1]), "=r"(r[2]), "=r"(r[3]) : "r"(addr));
}
__device__ __forceinline__ void ldsm_x2(uint32_t* r, uint32_t addr) {
    asm volatile("ldmatrix.sync.aligned.m8n8.x2.shared.b16 {%0,%1}, [%2];"
                 : "=r"(r[0]), "=r"(r[1]) : "r"(addr));
}

__device__ __forceinline__ void mma_bf16(float* c, const uint32_t* a, const uint32_t* b) {
    asm volatile(
        "mma.sync.aligned.m16n8k16.row.col.f32.bf16.bf16.f32 "
        "{%0,%1,%2,%3}, {%4,%5,%6,%7}, {%8,%9}, {%0,%1,%2,%3};"
        : "+f"(c[0]), "+f"(c[1]), "+f"(c[2]), "+f"(c[3])
        : "r"(a[0]), "r"(a[1]), "r"(a[2]), "r"(a[3]), "r"(b[0]), "r"(b[1]));
}

// ------------------------- patch embed + pos -------------------------------
__global__ void patch_embed_kernel(const float* __restrict__ x,
                                   const float* __restrict__ wconv,
                                   const float* __restrict__ bconv,
                                   const float* __restrict__ pos,
                                   float* __restrict__ h) {
    int bn = blockIdx.x;
    int b = bn >> 10, n = bn & 1023;
    int py = n >> 5, px = n & 31;
    __shared__ float patch[192];
    int tid = threadIdx.x;
    if (tid < 192) {
        int c = tid / 64;
        int rem = tid - c * 64;
        int i = rem >> 3, j = rem & 7;
        patch[tid] = x[(((size_t)(b * 3 + c) * 256) + (size_t)(py * 8 + i)) * 256
                       + (size_t)(px * 8 + j)];
    }
    __syncthreads();
    for (int d = tid; d < DD; d += 256) {
        const float* wr = wconv + (size_t)d * 192;
        float s = 0.f;
#pragma unroll
        for (int t = 0; t < 192; ++t) s += patch[t] * wr[t];
        h[(size_t)bn * DD + d] = s + bconv[d] + pos[(size_t)n * DD + d];
    }
}

// ---------------- layernorm -> bf16 hi/lo split ----------------------------
__global__ void layernorm_split_kernel(const float* __restrict__ h,
                                       const float* __restrict__ w,
                                       const float* __restrict__ bsh,
                                       __nv_bfloat16* __restrict__ yh,
                                       __nv_bfloat16* __restrict__ yl) {
    int row = blockIdx.x;
    const float* hr = h + (size_t)row * DD;
    int tid = threadIdx.x;
    float v0 = hr[tid], v1 = hr[tid + 256], v2 = hr[tid + 512];
    float s = v0 + v1 + v2;
    float sq = v0 * v0 + v1 * v1 + v2 * v2;
#pragma unroll
    for (int o = 16; o; o >>= 1) {
        s += __shfl_xor_sync(0xffffffffu, s, o);
        sq += __shfl_xor_sync(0xffffffffu, sq, o);
    }
    __shared__ float rs[8], rq[8];
    __shared__ float mean_s, rstd_s;
    int warp = tid >> 5, lane = tid & 31;
    if (lane == 0) { rs[warp] = s; rq[warp] = sq; }
    __syncthreads();
    if (tid == 0) {
        float S = 0.f, SQ = 0.f;
#pragma unroll
        for (int i = 0; i < 8; ++i) { S += rs[i]; SQ += rq[i]; }
        float m = S * (1.0f / DD);
        float var = SQ * (1.0f / DD) - m * m;
        mean_s = m;
        rstd_s = rsqrtf(var + 1e-5f);
    }
    __syncthreads();
    float m = mean_s, r = rstd_s;
    size_t base = (size_t)row * DD;
#pragma unroll
    for (int p = 0; p < 3; ++p) {
        int c = tid + p * 256;
        float vv = (p == 0 ? v0 : p == 1 ? v1 : v2);
        float val = (vv - m) * r * w[c] + bsh[c];
        __nv_bfloat16 hb = __float2bfloat16(val);
        yh[base + c] = hb;
        yl[base + c] = __float2bfloat16(val - __bfloat162float(hb));
    }
}

// ---------------- weight transpose + bf16 hi/lo split ----------------------
__global__ void wt_convert_kernel(const float* __restrict__ src,
                                  __nv_bfloat16* __restrict__ dhi,
                                  __nv_bfloat16* __restrict__ dlo,
                                  int K, int N) {
    __shared__ float t[32][33];
    int n0 = blockIdx.x * 32, k0 = blockIdx.y * 32;
    int tx = threadIdx.x & 31, ty = threadIdx.x >> 5;   // 32 x 8
#pragma unroll
    for (int i = 0; i < 32; i += 8)
        t[ty + i][tx] = src[(size_t)(k0 + ty + i) * N + n0 + tx];
    __syncthreads();
#pragma unroll
    for (int i = 0; i < 32; i += 8) {
        int n = n0 + ty + i, k = k0 + tx;
        float v = t[tx][ty + i];
        __nv_bfloat16 hb = __float2bfloat16(v);
        float lo = v - __bfloat162float(hb);
        dhi[(size_t)n * K + k] = hb;
        dlo[(size_t)n * K + k] = __float2bfloat16(lo);
    }
}

// -------------------- mma.sync GEMM: C = A @ Wt^T --------------------------
// A hi/lo [M,K] bf16 row-major, B hi/lo [N,K] bf16 row-major (== col-major B).
// CTA 128x128, 8 warps (2x4), warp tile 64x32, K-chunk 32, double-buffered.
#define EPI_STORE       0
#define EPI_BIAS_RES    2
#define EPI_GELU_SPLIT  3

#define KC        32
#define ROWB      80        // padded row bytes (32 bf16 = 64B + 16B pad)
#define ARR_BYTES 10240     // 128 rows * 80B
#define STG_BYTES 40960     // 4 arrays
#define SMEM_BYTES 81920    // 2 stages

template <int EPI>
__global__ void __launch_bounds__(256)
mma_gemm(const __nv_bfloat16* __restrict__ Ah, const __nv_bfloat16* __restrict__ Al,
         const __nv_bfloat16* __restrict__ Bh, const __nv_bfloat16* __restrict__ Bl,
         float* __restrict__ C, const float* __restrict__ bias,
         const float* __restrict__ res,
         __nv_bfloat16* __restrict__ Chi, __nv_bfloat16* __restrict__ Clo,
         int M, int Np, int K) {
    extern __shared__ char smem[];
    uint32_t sb = smem_u32(smem);
    int tid = threadIdx.x;
    int m0 = blockIdx.y * 128, n0 = blockIdx.x * 128;

    // ---------------- prefetch (cp.async) ----------------
    // 8 chunks of 16B per thread per stage: i/2 selects array {Ah,Al,Bh,Bl}
    const __nv_bfloat16* gsrc[4] = { Ah, Al, Bh, Bl };
    auto prefetch = [&](int st, int k0) {
        uint32_t sbase = sb + st * STG_BYTES;
#pragma unroll
        for (int i = 0; i < 8; ++i) {
            int arr = i >> 1;
            int c = tid + (i & 1) * 256;      // 0..511
            int row = c >> 2, q = c & 3;      // row, 16B quarter
            uint32_t soff = (uint32_t)arr * ARR_BYTES + row * ROWB + q * 16;
            size_t go = (arr < 2) ? ((size_t)(m0 + row) * K + k0)
                                  : ((size_t)(n0 + row) * K + k0);
            cp16(sbase + soff, gsrc[arr] + go + q * 8);
        }
        cp_commit();
    };

    int warp = tid >> 5, lane = tid & 31;
    int m_warp = (warp >> 2) * 64;       // 0 or 64
    int n_warp = (warp & 3) * 32;        // 0,32,64,96

    float acc[4][4][4];
#pragma unroll
    for (int i = 0; i < 4; ++i)
#pragma unroll
        for (int j = 0; j < 4; ++j)
#pragma unroll
            for (int q = 0; q < 4; ++q) acc[i][j][q] = 0.f;

    int arow = lane & 15;
    int acol = (lane >> 4) * 16;         // byte offset for k-half
    int brow = lane & 7;
    int bk   = ((lane >> 3) & 1) * 8;    // k offset for x2 matrix pair

    prefetch(0, 0);
    int nch = K / KC;
    for (int kt = 0; kt < nch; ++kt) {
        if (kt + 1 < nch) { prefetch((kt + 1) & 1, (kt + 1) * KC); cp_wait<1>(); }
        else              { cp_wait<0>(); }
        __syncthreads();

        uint32_t aB = sb + (kt & 1) * STG_BYTES;          // Ah
        uint32_t bB = aB + 2 * ARR_BYTES;                 // Bh
#pragma unroll
        for (int s16 = 0; s16 < 2; ++s16) {
            int kb2 = s16 * 32;                           // bytes (16 bf16)
            uint32_t ah[4][4], al[4][4], bhf[4][2], blf[4][2];
#pragma unroll
            for (int mb = 0; mb < 4; ++mb) {
                uint32_t addr = aB + (m_warp + mb * 16 + arow) * ROWB + kb2 + acol;
                ldsm_x4(ah[mb], addr);
                ldsm_x4(al[mb], addr + ARR_BYTES);
            }
#pragma unroll
            for (int nb = 0; nb < 4; ++nb) {
                uint32_t addr = bB + (n_warp + nb * 8 + brow) * ROWB + kb2 + bk * 2;
                ldsm_x2(bhf[nb], addr);
                ldsm_x2(blf[nb], addr + ARR_BYTES);
            }
#pragma unroll
            for (int mb = 0; mb < 4; ++mb)
#pragma unroll
                for (int nb = 0; nb < 4; ++nb) {
                    mma_bf16(acc[mb][nb], ah[mb], bhf[nb]);
                    mma_bf16(acc[mb][nb], ah[mb], blf[nb]);
                    mma_bf16(acc[mb][nb], al[mb], bhf[nb]);
                }
        }
        __syncthreads();
    }

    // ---------------- epilogue: regs -> gmem -----------------
#pragma unroll
    for (int mb = 0; mb < 4; ++mb) {
#pragma unroll
        for (int nb = 0; nb < 4; ++nb) {
            int r0 = m0 + m_warp + mb * 16 + (lane >> 2);
            int cc = n0 + n_warp + nb * 8 + (lane & 3) * 2;
            float* cp4 = acc[mb][nb];
#pragma unroll
            for (int half = 0; half < 2; ++half) {
                int rr = r0 + half * 8;
                float v0 = cp4[half * 2 + 0], v1 = cp4[half * 2 + 1];
                if (EPI == EPI_BIAS_RES) {
                    v0 += bias[cc]     + res[(size_t)rr * Np + cc];
                    v1 += bias[cc + 1] + res[(size_t)rr * Np + cc + 1];
                    float2 o2 = make_float2(v0, v1);
                    *reinterpret_cast<float2*>(C + (size_t)rr * Np + cc) = o2;
                } else if (EPI == EPI_GELU_SPLIT) {
                    v0 += bias[cc];
                    v1 += bias[cc + 1];
                    const float is2 = 0.70710678118654752f;
                    v0 = 0.5f * v0 * (1.0f + erff(v0 * is2));
                    v1 = 0.5f * v1 * (1.0f + erff(v1 * is2));
                    __nv_bfloat16 h0 = __float2bfloat16(v0);
                    __nv_bfloat16 h1 = __float2bfloat16(v1);
                    __nv_bfloat162 hi2(h0, h1);
                    __nv_bfloat162 lo2(__float2bfloat16(v0 - __bfloat162float(h0)),
                                       __float2bfloat16(v1 - __bfloat162float(h1)));
                    *reinterpret_cast<__nv_bfloat162*>(Chi + (size_t)rr * Np + cc) = hi2;
                    *reinterpret_cast<__nv_bfloat162*>(Clo + (size_t)rr * Np + cc) = lo2;
                } else {   // EPI_STORE
                    float2 o2 = make_float2(v0, v1);
                    *reinterpret_cast<float2*>(C + (size_t)rr * Np + cc) = o2;
                }
            }
        }
    }
}

// ------------------------ attention: Q @ K^T * scale -----------------------
__global__ void __launch_bounds__(256)
attn_scores_kernel(const float* __restrict__ qkv) {
    int bh = blockIdx.z;
    int b = bh / HEADS, hd = bh - b * HEADS;
    const float* Q  = qkv + (size_t)b * NTOK * QKV3 + hd * DH;
    const float* Kp = qkv + (size_t)b * NTOK * QKV3 + DD + hd * DH;
    float* Cp = g_scores + (size_t)bh * NTOK * NTOK;

    int m0 = blockIdx.y * 64, n0 = blockIdx.x * 64;
    __shared__ float Qs[64][68];
    __shared__ float Ks[64][68];
    int tid = threadIdx.x;
    int r = tid >> 2;
    int c4 = (tid & 3) * 4;
#pragma unroll
    for (int p = 0; p < 4; ++p) {
        int kc = c4 + p * 16;
        float4 q = *(const float4*)(Q + (size_t)(m0 + r) * QKV3 + kc);
        Qs[kc + 0][r] = q.x; Qs[kc + 1][r] = q.y; Qs[kc + 2][r] = q.z; Qs[kc + 3][r] = q.w;
        float4 kk = *(const float4*)(Kp + (size_t)(n0 + r) * QKV3 + kc);
        Ks[kc + 0][r] = kk.x; Ks[kc + 1][r] = kk.y; Ks[kc + 2][r] = kk.z; Ks[kc + 3][r] = kk.w;
    }
    __syncthreads();

    int tx = tid & 15, ty = tid >> 4;
    float acc[4][4];
#pragma unroll
    for (int i = 0; i < 4; ++i)
#pragma unroll
        for (int j = 0; j < 4; ++j) acc[i][j] = 0.f;

#pragma unroll 8
    for (int k = 0; k < 64; ++k) {
        float ar[4], br[4];
        *(float4*)&ar[0] = *(const float4*)&Qs[k][ty * 4];
        *(float4*)&br[0] = *(const float4*)&Ks[k][tx * 4];
#pragma unroll
        for (int i = 0; i < 4; ++i)
#pragma unroll
            for (int j = 0; j < 4; ++j) acc[i][j] += ar[i] * br[j];
    }
    const float scale = 0.125f;
#pragma unroll
    for (int i = 0; i < 4; ++i)
#pragma unroll
        for (int j = 0; j < 4; ++j)
            Cp[(size_t)(m0 + ty * 4 + i) * NTOK + n0 + tx * 4 + j] = acc[i][j] * scale;
}

// ------------------------------- softmax -----------------------------------
__global__ void softmax_kernel() {
    float* row = g_scores + (size_t)blockIdx.x * NTOK;
    int tid = threadIdx.x;
    float v[4];
#pragma unroll
    for (int i = 0; i < 4; ++i) v[i] = row[tid + 256 * i];
    float mx = fmaxf(fmaxf(v[0], v[1]), fmaxf(v[2], v[3]));
#pragma unroll
    for (int o = 16; o; o >>= 1) mx = fmaxf(mx, __shfl_xor_sync(0xffffffffu, mx, o));
    __shared__ float red[8];
    __shared__ float bmax, binv;
    int warp = tid >> 5, lane = tid & 31;
    if (lane == 0) red[warp] = mx;
    __syncthreads();
    if (tid == 0) {
        float m = red[0];
#pragma unroll
        for (int i = 1; i < 8; ++i) m = fmaxf(m, red[i]);
        bmax = m;
    }
    __syncthreads();
    mx = bmax;
    float sum = 0.f;
#pragma unroll
    for (int i = 0; i < 4; ++i) { v[i] = __expf(v[i] - mx); sum += v[i]; }
#pragma unroll
    for (int o = 16; o; o >>= 1) sum += __shfl_xor_sync(0xffffffffu, sum, o);
    if (lane == 0) red[warp] = sum;
    __syncthreads();
    if (tid == 0) {
        float S = 0.f;
#pragma unroll
        for (int i = 0; i < 8; ++i) S += red[i];
        binv = 1.0f / S;
    }
    __syncthreads();
    float inv = binv;
#pragma unroll
    for (int i = 0; i < 4; ++i) row[tid + 256 * i] = v[i] * inv;
}

// ------------ attention: P @ V  -> o as bf16 hi/lo split -------------------
__global__ void __launch_bounds__(256)
attn_v_kernel(const float* __restrict__ qkv,
              __nv_bfloat16* __restrict__ oh, __nv_bfloat16* __restrict__ ol) {
    int bh = blockIdx.y;
    int b = bh / HEADS, hd = bh - b * HEADS;
    const float* Ap = g_scores + (size_t)bh * NTOK * NTOK;
    const float* Vp = qkv + (size_t)b * NTOK * QKV3 + 2 * DD + hd * DH;
    int m0 = blockIdx.x * 64;

    __shared__ float As2[64][68];
    __shared__ float Vs[64][68];
    int tid = threadIdx.x;
    int r = tid >> 2;
    int c4 = (tid & 3) * 4;
    int tx = tid & 15, ty = tid >> 4;

    float acc[4][4];
#pragma unroll
    for (int i = 0; i < 4; ++i)
#pragma unroll
        for (int j = 0; j < 4; ++j) acc[i][j] = 0.f;

    for (int kt = 0; kt < NTOK / 64; ++kt) {
#pragma unroll
        for (int p = 0; p < 4; ++p) {
            int kc = c4 + p * 16;
            float4 a = *(const float4*)(Ap + (size_t)(m0 + r) * NTOK + kt * 64 + kc);
            As2[kc + 0][r] = a.x; As2[kc + 1][r] = a.y; As2[kc + 2][r] = a.z; As2[kc + 3][r] = a.w;
            float4 vv = *(const float4*)(Vp + (size_t)(kt * 64 + r) * QKV3 + kc);
            *(float4*)&Vs[r][kc] = vv;
        }
        __syncthreads();
#pragma unroll 8
        for (int k = 0; k < 64; ++k) {
            float ar[4], br[4];
            *(float4*)&ar[0] = *(const float4*)&As2[k][ty * 4];
            *(float4*)&br[0] = *(const float4*)&Vs[k][tx * 4];
#pragma unroll
            for (int i = 0; i < 4; ++i)
#pragma unroll
                for (int j = 0; j < 4; ++j) acc[i][j] += ar[i] * br[j];
        }
        __syncthreads();
    }
#pragma unroll
    for (int i = 0; i < 4; ++i)
#pragma unroll
        for (int j = 0; j < 4; ++j) {
            size_t idx = (size_t)(b * NTOK + m0 + ty * 4 + i) * DD + hd * DH + tx * 4 + j;
            float v = acc[i][j];
            __nv_bfloat16 hb = __float2bfloat16(v);
            oh[idx] = hb;
            ol[idx] = __float2bfloat16(v - __bfloat162float(hb));
        }
}

// ------------------------------- launcher ----------------------------------
extern "C" void kernel_launch(void* const* d_in, const int* in_sizes, int n_in,
                              void* d_out, int out_size) {
    const float* x       = (const float*)d_in[0];
    const float* w_conv  = (const float*)d_in[1];
    const float* b_conv  = (const float*)d_in[2];
    const float* pos_emb = (const float*)d_in[3];
    const float* ln1_w   = (const float*)d_in[4];
    const float* ln1_b   = (const float*)d_in[5];
    const float* qkv_w   = (const float*)d_in[6];
    const float* out_w   = (const float*)d_in[7];
    const float* out_b   = (const float*)d_in[8];
    const float* ln2_w   = (const float*)d_in[9];
    const float* ln2_b   = (const float*)d_in[10];
    const float* w1      = (const float*)d_in[11];
    const float* b1      = (const float*)d_in[12];
    const float* w2      = (const float*)d_in[13];
    const float* b2      = (const float*)d_in[14];

    float* h = (float*)d_out;

    float *qkvb;
    cudaGetSymbolAddress((void**)&qkvb, g_qkv);
    __nv_bfloat16 *yh, *yl, *oh, *ol, *mh, *ml;
    cudaGetSymbolAddress((void**)&yh, g_yh);
    cudaGetSymbolAddress((void**)&yl, g_yl);
    cudaGetSymbolAddress((void**)&oh, g_oh);
    cudaGetSymbolAddress((void**)&ol, g_ol);
    cudaGetSymbolAddress((void**)&mh, g_mh);
    cudaGetSymbolAddress((void**)&ml, g_ml);

    __nv_bfloat16 *wqh, *wql, *woh, *wol, *w1h, *w1l, *w2h, *w2l;
    cudaGetSymbolAddress((void**)&wqh, g_wq_hi);
    cudaGetSymbolAddress((void**)&wql, g_wq_lo);
    cudaGetSymbolAddress((void**)&woh, g_wo_hi);
    cudaGetSymbolAddress((void**)&wol, g_wo_lo);
    cudaGetSymbolAddress((void**)&w1h, g_w1_hi);
    cudaGetSymbolAddress((void**)&w1l, g_w1_lo);
    cudaGetSymbolAddress((void**)&w2h, g_w2_hi);
    cudaGetSymbolAddress((void**)&w2l, g_w2_lo);

    cudaFuncSetAttribute(mma_gemm<EPI_STORE>,
                         cudaFuncAttributeMaxDynamicSharedMemorySize, SMEM_BYTES);
    cudaFuncSetAttribute(mma_gemm<EPI_BIAS_RES>,
                         cudaFuncAttributeMaxDynamicSharedMemorySize, SMEM_BYTES);
    cudaFuncSetAttribute(mma_gemm<EPI_GELU_SPLIT>,
                         cudaFuncAttributeMaxDynamicSharedMemorySize, SMEM_BYTES);

    patch_embed_kernel<<<BN_, 256>>>(x, w_conv, b_conv, pos_emb, h);

    // weight transpose + bf16 split (once per launch, all layers)
    for (int L = 0; L < DEPTH; ++L) {
        wt_convert_kernel<<<dim3(QKV3 / 32, DD / 32), 256>>>(
            qkv_w + (size_t)L * DD * QKV3,
            wqh + (size_t)L * QKV3 * DD, wql + (size_t)L * QKV3 * DD, DD, QKV3);
        wt_convert_kernel<<<dim3(DD / 32, DD / 32), 256>>>(
            out_w + (size_t)L * DD * DD,
            woh + (size_t)L * DD * DD, wol + (size_t)L * DD * DD, DD, DD);
        wt_convert_kernel<<<dim3(MLPD / 32, DD / 32), 256>>>(
            w1 + (size_t)L * DD * MLPD,
            w1h + (size_t)L * MLPD * DD, w1l + (size_t)L * MLPD * DD, DD, MLPD);
        wt_convert_kernel<<<dim3(DD / 32, MLPD / 32), 256>>>(
            w2 + (size_t)L * MLPD * DD,
            w2h + (size_t)L * DD * MLPD, w2l + (size_t)L * DD * MLPD, MLPD, DD);
    }

    for (int L = 0; L < DEPTH; ++L) {
        // --- MHSA ---
        layernorm_split_kernel<<<BN_, 256>>>(h, ln1_w + L * DD, ln1_b + L * DD, yh, yl);

        mma_gemm<EPI_STORE><<<dim3(QKV3 / 128, BN_ / 128), 256, SMEM_BYTES>>>(
            yh, yl, wqh + (size_t)L * QKV3 * DD, wql + (size_t)L * QKV3 * DD,
            qkvb, nullptr, nullptr, nullptr, nullptr, BN_, QKV3, DD);

        dim3 gs(NTOK / 64, NTOK / 64, BB * HEADS);
        attn_scores_kernel<<<gs, 256>>>(qkvb);

        softmax_kernel<<<BB * HEADS * NTOK, 256>>>();

        dim3 gv(NTOK / 64, BB * HEADS);
        attn_v_kernel<<<gv, 256>>>(qkvb, oh, ol);

        mma_gemm<EPI_BIAS_RES><<<dim3(DD / 128, BN_ / 128), 256, SMEM_BYTES>>>(
            oh, ol, woh + (size_t)L * DD * DD, wol + (size_t)L * DD * DD,
            h, out_b + L * DD, h, nullptr, nullptr, BN_, DD, DD);

        // --- FFN ---
        layernorm_split_kernel<<<BN_, 256>>>(h, ln2_w + L * DD, ln2_b + L * DD, yh, yl);

        mma_gemm<EPI_GELU_SPLIT><<<dim3(MLPD / 128, BN_ / 128), 256, SMEM_BYTES>>>(
            yh, yl, w1h + (size_t)L * MLPD * DD, w1l + (size_t)L * MLPD * DD,
            nullptr, b1 + L * MLPD, nullptr, mh, ml, BN_, MLPD, DD);

        mma_gemm<EPI_BIAS_RES><<<dim3(DD / 128, BN_ / 128), 256, SMEM_BYTES>>>(
            mh, ml, w2h + (size_t)L * DD * MLPD, w2l + (size_t)L * DD * MLPD,
            h, b2 + L * DD, h, nullptr, nullptr, BN_, DD, MLPD);
    }
    (void)in_sizes; (void)n_in; (void)out_size;
}

// round 13
// speedup vs baseline: 1.6848x; 1.0373x over previous
#include <cuda_runtime.h>
#include <cuda_bf16.h>
#include <cstdint>
#include <cstddef>

// ---------------------------------------------------------------------------
// ViT-Base encoder. Round 12 — bisect build:
//  - GEMMs: XOR-swizzled smem (conflict-free ldmatrix) + 3-stage cp.async (NEW)
//  - Attention: R7 known-good SIMT path (scores / softmax / PV)  (REVERTED)
// B=8, N=1024 tokens, D=768, 8 layers, 12 heads x 64, MLP=3072.
// ---------------------------------------------------------------------------

#define BB    8
#define NTOK  1024
#define DD    768
#define DEPTH 8
#define HEADS 12
#define DH    64
#define MLPD  3072
#define BN_   (BB * NTOK)          // 8192 rows
#define QKV3  (3 * DD)             // 2304

// ----------------------------- scratch -------------------------------------
__device__ float g_qkv[(size_t)BN_ * QKV3];
__device__ float g_scores[(size_t)BB * HEADS * NTOK * NTOK];

// activation bf16 hi/lo (GEMM A operands)
__device__ __nv_bfloat16 g_yh[(size_t)BN_ * DD];
__device__ __nv_bfloat16 g_yl[(size_t)BN_ * DD];
__device__ __nv_bfloat16 g_oh[(size_t)BN_ * DD];
__device__ __nv_bfloat16 g_ol[(size_t)BN_ * DD];
__device__ __nv_bfloat16 g_mh[(size_t)BN_ * MLPD];
__device__ __nv_bfloat16 g_ml[(size_t)BN_ * MLPD];

// transposed + bf16-split weights: Wt[n][k] = W[k][n]
__device__ __nv_bfloat16 g_wq_hi[(size_t)DEPTH * QKV3 * DD];
__device__ __nv_bfloat16 g_wq_lo[(size_t)DEPTH * QKV3 * DD];
__device__ __nv_bfloat16 g_wo_hi[(size_t)DEPTH * DD * DD];
__device__ __nv_bfloat16 g_wo_lo[(size_t)DEPTH * DD * DD];
__device__ __nv_bfloat16 g_w1_hi[(size_t)DEPTH * MLPD * DD];
__device__ __nv_bfloat16 g_w1_lo[(size_t)DEPTH * MLPD * DD];
__device__ __nv_bfloat16 g_w2_hi[(size_t)DEPTH * DD * MLPD];
__device__ __nv_bfloat16 g_w2_lo[(size_t)DEPTH * DD * MLPD];

// --------------------------- PTX helpers -----------------------------------
__device__ __forceinline__ uint32_t smem_u32(const void* p) {
    uint32_t a;
    asm("{ .reg .u64 t; cvta.to.shared.u64 t, %1; cvt.u32.u64 %0, t; }"
        : "=r"(a) : "l"(p));
    return a;
}
__device__ __forceinline__ void cp16(uint32_t s, const void* g) {
    asm volatile("cp.async.cg.shared.global [%0], [%1], 16;" :: "r"(s), "l"(g));
}
__device__ __forceinline__ void cp_commit() {
    asm volatile("cp.async.commit_group;" ::: "memory");
}
template <int N>
__device__ __forceinline__ void cp_wait() {
    asm volatile("cp.async.wait_group %0;" :: "n"(N) : "memory");
}
__device__ __forceinline__ void ldsm_x4(uint32_t* r, uint32_t addr) {
    asm volatile("ldmatrix.sync.aligned.m8n8.x4.shared.b16 {%0,%1,%2,%3}, [%4];"
                 : "=r"(r[0]), "=r"(r[1]), "=r"(r[2]), "=r"(r[3]) : "r"(addr));
}
__device__ __forceinline__ void ldsm_x2(uint32_t* r, uint32_t addr) {
    asm volatile("ldmatrix.sync.aligned.m8n8.x2.shared.b16 {%0,%1}, [%2];"
                 : "=r"(r[0]), "=r"(r[1]) : "r"(addr));
}
__device__ __forceinline__ void mma_bf16(float* c, const uint32_t* a, const uint32_t* b) {
    asm volatile(
        "mma.sync.aligned.m16n8k16.row.col.f32.bf16.bf16.f32 "
        "{%0,%1,%2,%3}, {%4,%5,%6,%7}, {%8,%9}, {%0,%1,%2,%3};"
        : "+f"(c[0]), "+f"(c[1]), "+f"(c[2]), "+f"(c[3])
        : "r"(a[0]), "r"(a[1]), "r"(a[2]), "r"(a[3]), "r"(b[0]), "r"(b[1]));
}
__device__ __forceinline__ uint32_t pack_bf2(__nv_bfloat16 a, __nv_bfloat16 b) {
    __nv_bfloat162 t(a, b);               // a = low element
    return *reinterpret_cast<uint32_t*>(&t);
}

// ------------------------- patch embed + pos -------------------------------
__global__ void patch_embed_kernel(const float* __restrict__ x,
                                   const float* __restrict__ wconv,
                                   const float* __restrict__ bconv,
                                   const float* __restrict__ pos,
                                   float* __restrict__ h) {
    int bn = blockIdx.x;
    int b = bn >> 10, n = bn & 1023;
    int py = n >> 5, px = n & 31;
    __shared__ float patch[192];
    int tid = threadIdx.x;
    if (tid < 192) {
        int c = tid / 64;
        int rem = tid - c * 64;
        int i = rem >> 3, j = rem & 7;
        patch[tid] = x[(((size_t)(b * 3 + c) * 256) + (size_t)(py * 8 + i)) * 256
                       + (size_t)(px * 8 + j)];
    }
    __syncthreads();
    for (int d = tid; d < DD; d += 256) {
        const float* wr = wconv + (size_t)d * 192;
        float s = 0.f;
#pragma unroll
        for (int t = 0; t < 192; ++t) s += patch[t] * wr[t];
        h[(size_t)bn * DD + d] = s + bconv[d] + pos[(size_t)n * DD + d];
    }
}

// ---------------- layernorm -> bf16 hi/lo split ----------------------------
__global__ void layernorm_split_kernel(const float* __restrict__ h,
                                       const float* __restrict__ w,
                                       const float* __restrict__ bsh,
                                       __nv_bfloat16* __restrict__ yh,
                                       __nv_bfloat16* __restrict__ yl) {
    int row = blockIdx.x;
    const float* hr = h + (size_t)row * DD;
    int tid = threadIdx.x;
    float v0 = hr[tid], v1 = hr[tid + 256], v2 = hr[tid + 512];
    float s = v0 + v1 + v2;
    float sq = v0 * v0 + v1 * v1 + v2 * v2;
#pragma unroll
    for (int o = 16; o; o >>= 1) {
        s += __shfl_xor_sync(0xffffffffu, s, o);
        sq += __shfl_xor_sync(0xffffffffu, sq, o);
    }
    __shared__ float rs[8], rq[8];
    __shared__ float mean_s, rstd_s;
    int warp = tid >> 5, lane = tid & 31;
    if (lane == 0) { rs[warp] = s; rq[warp] = sq; }
    __syncthreads();
    if (tid == 0) {
        float S = 0.f, SQ = 0.f;
#pragma unroll
        for (int i = 0; i < 8; ++i) { S += rs[i]; SQ += rq[i]; }
        float m = S * (1.0f / DD);
        float var = SQ * (1.0f / DD) - m * m;
        mean_s = m;
        rstd_s = rsqrtf(var + 1e-5f);
    }
    __syncthreads();
    float m = mean_s, r = rstd_s;
    size_t base = (size_t)row * DD;
#pragma unroll
    for (int p = 0; p < 3; ++p) {
        int c = tid + p * 256;
        float vv = (p == 0 ? v0 : p == 1 ? v1 : v2);
        float val = (vv - m) * r * w[c] + bsh[c];
        __nv_bfloat16 hb = __float2bfloat16(val);
        yh[base + c] = hb;
        yl[base + c] = __float2bfloat16(val - __bfloat162float(hb));
    }
}

// ---------------- weight transpose + bf16 hi/lo split ----------------------
__global__ void wt_convert_kernel(const float* __restrict__ src,
                                  __nv_bfloat16* __restrict__ dhi,
                                  __nv_bfloat16* __restrict__ dlo,
                                  int K, int N) {
    __shared__ float t[32][33];
    int n0 = blockIdx.x * 32, k0 = blockIdx.y * 32;
    int tx = threadIdx.x & 31, ty = threadIdx.x >> 5;
#pragma unroll
    for (int i = 0; i < 32; i += 8)
        t[ty + i][tx] = src[(size_t)(k0 + ty + i) * N + n0 + tx];
    __syncthreads();
#pragma unroll
    for (int i = 0; i < 32; i += 8) {
        int n = n0 + ty + i, k = k0 + tx;
        float v = t[tx][ty + i];
        __nv_bfloat16 hb = __float2bfloat16(v);
        dhi[(size_t)n * K + k] = hb;
        dlo[(size_t)n * K + k] = __float2bfloat16(v - __bfloat162float(hb));
    }
}

// -------------------- mma.sync GEMM: C = A @ Wt^T --------------------------
// CTA 128x128, 8 warps (2x4), warp tile 64x32, K-chunk 32, 3-stage cp.async.
// Smem rows: 64 B (32 bf16), XOR swizzle chunk ^= (row>>1)&3 -> conflict-free.
#define EPI_STORE       0
#define EPI_BIAS_RES    2
#define EPI_GELU_SPLIT  3

#define KC        32
#define ARR       8192      // 128 rows * 64 B
#define STG       32768     // 4 arrays
#define SMEM_BYTES 98304    // 3 stages

template <int EPI>
__global__ void __launch_bounds__(256)
mma_gemm(const __nv_bfloat16* __restrict__ Ah, const __nv_bfloat16* __restrict__ Al,
         const __nv_bfloat16* __restrict__ Bh, const __nv_bfloat16* __restrict__ Bl,
         float* __restrict__ C, const float* __restrict__ bias,
         const float* __restrict__ res,
         __nv_bfloat16* __restrict__ Chi, __nv_bfloat16* __restrict__ Clo,
         int M, int Np, int K) {
    extern __shared__ char smem[];
    uint32_t sb = smem_u32(smem);
    int tid = threadIdx.x;
    int m0 = blockIdx.y * 128, n0 = blockIdx.x * 128;

    const __nv_bfloat16* gsrc[4] = { Ah, Al, Bh, Bl };
    auto prefetch = [&](int st, int k0) {
        uint32_t sbase = sb + st * STG;
#pragma unroll
        for (int i = 0; i < 8; ++i) {
            int arr = i >> 1;
            int c = tid + (i & 1) * 256;      // 0..511
            int row = c >> 2, q = c & 3;
            uint32_t soff = (uint32_t)arr * ARR + row * 64
                          + ((q ^ ((row >> 1) & 3)) << 4);
            size_t go = (arr < 2) ? ((size_t)(m0 + row) * K + k0)
                                  : ((size_t)(n0 + row) * K + k0);
            cp16(sbase + soff, gsrc[arr] + go + q * 8);
        }
        cp_commit();
    };

    int warp = tid >> 5, lane = tid & 31;
    int m_warp = (warp >> 2) * 64;
    int n_warp = (warp & 3) * 32;

    float acc[4][4][4];
#pragma unroll
    for (int i = 0; i < 4; ++i)
#pragma unroll
        for (int j = 0; j < 4; ++j)
#pragma unroll
            for (int q = 0; q < 4; ++q) acc[i][j][q] = 0.f;

    prefetch(0, 0);
    prefetch(1, KC);
    int nch = K / KC;
    for (int kt = 0; kt < nch; ++kt) {
        if (kt + 2 < nch)      { prefetch((kt + 2) % 3, (kt + 2) * KC); cp_wait<2>(); }
        else if (kt + 1 < nch) { cp_wait<1>(); }
        else                   { cp_wait<0>(); }
        __syncthreads();

        uint32_t aB = sb + (kt % 3) * STG;    // Ah
        uint32_t bB = aB + 2 * ARR;           // Bh
#pragma unroll
        for (int s16 = 0; s16 < 2; ++s16) {
            uint32_t ah[4][4], al[4][4], bhf[4][2], blf[4][2];
#pragma unroll
            for (int mb = 0; mb < 4; ++mb) {
                int row = m_warp + mb * 16 + (lane & 15);
                int lch = s16 * 2 + (lane >> 4);
                uint32_t o = row * 64 + ((lch ^ ((row >> 1) & 3)) << 4);
                ldsm_x4(ah[mb], aB + o);
                ldsm_x4(al[mb], aB + ARR + o);
            }
#pragma unroll
            for (int nb = 0; nb < 4; ++nb) {
                int rown = n_warp + nb * 8 + (lane & 7);
                int lch = s16 * 2 + ((lane >> 3) & 1);
                uint32_t o = rown * 64 + ((lch ^ ((rown >> 1) & 3)) << 4);
                ldsm_x2(bhf[nb], bB + o);
                ldsm_x2(blf[nb], bB + ARR + o);
            }
#pragma unroll
            for (int mb = 0; mb < 4; ++mb)
#pragma unroll
                for (int nb = 0; nb < 4; ++nb) {
                    mma_bf16(acc[mb][nb], ah[mb], bhf[nb]);
                    mma_bf16(acc[mb][nb], ah[mb], blf[nb]);
                    mma_bf16(acc[mb][nb], al[mb], bhf[nb]);
                }
        }
        __syncthreads();
    }

    // ---------------- epilogue ----------------
#pragma unroll
    for (int mb = 0; mb < 4; ++mb) {
#pragma unroll
        for (int nb = 0; nb < 4; ++nb) {
            int r0 = m0 + m_warp + mb * 16 + (lane >> 2);
            int cc = n0 + n_warp + nb * 8 + (lane & 3) * 2;
            float* cp4 = acc[mb][nb];
#pragma unroll
            for (int half = 0; half < 2; ++half) {
                int rr = r0 + half * 8;
                float v0 = cp4[half * 2 + 0], v1 = cp4[half * 2 + 1];
                if (EPI == EPI_BIAS_RES) {
                    v0 += bias[cc]     + res[(size_t)rr * Np + cc];
                    v1 += bias[cc + 1] + res[(size_t)rr * Np + cc + 1];
                    *reinterpret_cast<float2*>(C + (size_t)rr * Np + cc) =
                        make_float2(v0, v1);
                } else if (EPI == EPI_GELU_SPLIT) {
                    v0 += bias[cc];
                    v1 += bias[cc + 1];
                    const float is2 = 0.70710678118654752f;
                    v0 = 0.5f * v0 * (1.0f + erff(v0 * is2));
                    v1 = 0.5f * v1 * (1.0f + erff(v1 * is2));
                    __nv_bfloat16 h0 = __float2bfloat16(v0);
                    __nv_bfloat16 h1 = __float2bfloat16(v1);
                    *reinterpret_cast<uint32_t*>(Chi + (size_t)rr * Np + cc) = pack_bf2(h0, h1);
                    *reinterpret_cast<uint32_t*>(Clo + (size_t)rr * Np + cc) =
                        pack_bf2(__float2bfloat16(v0 - __bfloat162float(h0)),
                                 __float2bfloat16(v1 - __bfloat162float(h1)));
                } else {   // EPI_STORE: plain f32 store
                    *reinterpret_cast<float2*>(C + (size_t)rr * Np + cc) =
                        make_float2(v0, v1);
                }
            }
        }
    }
}

// ------------------------ attention: Q @ K^T * scale -----------------------
__global__ void __launch_bounds__(256)
attn_scores_kernel(const float* __restrict__ qkv) {
    int bh = blockIdx.z;
    int b = bh / HEADS, hd = bh - b * HEADS;
    const float* Q  = qkv + (size_t)b * NTOK * QKV3 + hd * DH;
    const float* Kp = qkv + (size_t)b * NTOK * QKV3 + DD + hd * DH;
    float* Cp = g_scores + (size_t)bh * NTOK * NTOK;

    int m0 = blockIdx.y * 64, n0 = blockIdx.x * 64;
    __shared__ float Qs[64][68];
    __shared__ float Ks[64][68];
    int tid = threadIdx.x;
    int r = tid >> 2;
    int c4 = (tid & 3) * 4;
#pragma unroll
    for (int p = 0; p < 4; ++p) {
        int kc = c4 + p * 16;
        float4 q = *(const float4*)(Q + (size_t)(m0 + r) * QKV3 + kc);
        Qs[kc + 0][r] = q.x; Qs[kc + 1][r] = q.y; Qs[kc + 2][r] = q.z; Qs[kc + 3][r] = q.w;
        float4 kk = *(const float4*)(Kp + (size_t)(n0 + r) * QKV3 + kc);
        Ks[kc + 0][r] = kk.x; Ks[kc + 1][r] = kk.y; Ks[kc + 2][r] = kk.z; Ks[kc + 3][r] = kk.w;
    }
    __syncthreads();

    int tx = tid & 15, ty = tid >> 4;
    float acc[4][4];
#pragma unroll
    for (int i = 0; i < 4; ++i)
#pragma unroll
        for (int j = 0; j < 4; ++j) acc[i][j] = 0.f;

#pragma unroll 8
    for (int k = 0; k < 64; ++k) {
        float ar[4], br[4];
        *(float4*)&ar[0] = *(const float4*)&Qs[k][ty * 4];
        *(float4*)&br[0] = *(const float4*)&Ks[k][tx * 4];
#pragma unroll
        for (int i = 0; i < 4; ++i)
#pragma unroll
            for (int j = 0; j < 4; ++j) acc[i][j] += ar[i] * br[j];
    }
    const float scale = 0.125f;
#pragma unroll
    for (int i = 0; i < 4; ++i)
#pragma unroll
        for (int j = 0; j < 4; ++j)
            Cp[(size_t)(m0 + ty * 4 + i) * NTOK + n0 + tx * 4 + j] = acc[i][j] * scale;
}

// ------------------------------- softmax -----------------------------------
__global__ void softmax_kernel() {
    float* row = g_scores + (size_t)blockIdx.x * NTOK;
    int tid = threadIdx.x;
    float v[4];
#pragma unroll
    for (int i = 0; i < 4; ++i) v[i] = row[tid + 256 * i];
    float mx = fmaxf(fmaxf(v[0], v[1]), fmaxf(v[2], v[3]));
#pragma unroll
    for (int o = 16; o; o >>= 1) mx = fmaxf(mx, __shfl_xor_sync(0xffffffffu, mx, o));
    __shared__ float red[8];
    __shared__ float bmax, binv;
    int warp = tid >> 5, lane = tid & 31;
    if (lane == 0) red[warp] = mx;
    __syncthreads();
    if (tid == 0) {
        float m = red[0];
#pragma unroll
        for (int i = 1; i < 8; ++i) m = fmaxf(m, red[i]);
        bmax = m;
    }
    __syncthreads();
    mx = bmax;
    float sum = 0.f;
#pragma unroll
    for (int i = 0; i < 4; ++i) { v[i] = __expf(v[i] - mx); sum += v[i]; }
#pragma unroll
    for (int o = 16; o; o >>= 1) sum += __shfl_xor_sync(0xffffffffu, sum, o);
    if (lane == 0) red[warp] = sum;
    __syncthreads();
    if (tid == 0) {
        float S = 0.f;
#pragma unroll
        for (int i = 0; i < 8; ++i) S += red[i];
        binv = 1.0f / S;
    }
    __syncthreads();
    float inv = binv;
#pragma unroll
    for (int i = 0; i < 4; ++i) row[tid + 256 * i] = v[i] * inv;
}

// ------------ attention: P @ V  -> o as bf16 hi/lo split -------------------
__global__ void __launch_bounds__(256)
attn_v_kernel(const float* __restrict__ qkv,
              __nv_bfloat16* __restrict__ oh, __nv_bfloat16* __restrict__ ol) {
    int bh = blockIdx.y;
    int b = bh / HEADS, hd = bh - b * HEADS;
    const float* Ap = g_scores + (size_t)bh * NTOK * NTOK;
    const float* Vp = qkv + (size_t)b * NTOK * QKV3 + 2 * DD + hd * DH;
    int m0 = blockIdx.x * 64;

    __shared__ float As2[64][68];
    __shared__ float Vs[64][68];
    int tid = threadIdx.x;
    int r = tid >> 2;
    int c4 = (tid & 3) * 4;
    int tx = tid & 15, ty = tid >> 4;

    float acc[4][4];
#pragma unroll
    for (int i = 0; i < 4; ++i)
#pragma unroll
        for (int j = 0; j < 4; ++j) acc[i][j] = 0.f;

    for (int kt = 0; kt < NTOK / 64; ++kt) {
#pragma unroll
        for (int p = 0; p < 4; ++p) {
            int kc = c4 + p * 16;
            float4 a = *(const float4*)(Ap + (size_t)(m0 + r) * NTOK + kt * 64 + kc);
            As2[kc + 0][r] = a.x; As2[kc + 1][r] = a.y; As2[kc + 2][r] = a.z; As2[kc + 3][r] = a.w;
            float4 vv = *(const float4*)(Vp + (size_t)(kt * 64 + r) * QKV3 + kc);
            *(float4*)&Vs[r][kc] = vv;
        }
        __syncthreads();
#pragma unroll 8
        for (int k = 0; k < 64; ++k) {
            float ar[4], br[4];
            *(float4*)&ar[0] = *(const float4*)&As2[k][ty * 4];
            *(float4*)&br[0] = *(const float4*)&Vs[k][tx * 4];
#pragma unroll
            for (int i = 0; i < 4; ++i)
#pragma unroll
                for (int j = 0; j < 4; ++j) acc[i][j] += ar[i] * br[j];
        }
        __syncthreads();
    }
#pragma unroll
    for (int i = 0; i < 4; ++i)
#pragma unroll
        for (int j = 0; j < 4; ++j) {
            size_t idx = (size_t)(b * NTOK + m0 + ty * 4 + i) * DD + hd * DH + tx * 4 + j;
            float v = acc[i][j];
            __nv_bfloat16 hb = __float2bfloat16(v);
            oh[idx] = hb;
            ol[idx] = __float2bfloat16(v - __bfloat162float(hb));
        }
}

// ------------------------------- launcher ----------------------------------
extern "C" void kernel_launch(void* const* d_in, const int* in_sizes, int n_in,
                              void* d_out, int out_size) {
    const float* x       = (const float*)d_in[0];
    const float* w_conv  = (const float*)d_in[1];
    const float* b_conv  = (const float*)d_in[2];
    const float* pos_emb = (const float*)d_in[3];
    const float* ln1_w   = (const float*)d_in[4];
    const float* ln1_b   = (const float*)d_in[5];
    const float* qkv_w   = (const float*)d_in[6];
    const float* out_w   = (const float*)d_in[7];
    const float* out_b   = (const float*)d_in[8];
    const float* ln2_w   = (const float*)d_in[9];
    const float* ln2_b   = (const float*)d_in[10];
    const float* w1      = (const float*)d_in[11];
    const float* b1      = (const float*)d_in[12];
    const float* w2      = (const float*)d_in[13];
    const float* b2      = (const float*)d_in[14];

    float* h = (float*)d_out;

    float* qkvb;
    cudaGetSymbolAddress((void**)&qkvb, g_qkv);
    __nv_bfloat16 *yh, *yl, *oh, *ol, *mh, *ml;
    cudaGetSymbolAddress((void**)&yh, g_yh);
    cudaGetSymbolAddress((void**)&yl, g_yl);
    cudaGetSymbolAddress((void**)&oh, g_oh);
    cudaGetSymbolAddress((void**)&ol, g_ol);
    cudaGetSymbolAddress((void**)&mh, g_mh);
    cudaGetSymbolAddress((void**)&ml, g_ml);

    __nv_bfloat16 *wqh, *wql, *woh, *wol, *w1h, *w1l, *w2h, *w2l;
    cudaGetSymbolAddress((void**)&wqh, g_wq_hi);
    cudaGetSymbolAddress((void**)&wql, g_wq_lo);
    cudaGetSymbolAddress((void**)&woh, g_wo_hi);
    cudaGetSymbolAddress((void**)&wol, g_wo_lo);
    cudaGetSymbolAddress((void**)&w1h, g_w1_hi);
    cudaGetSymbolAddress((void**)&w1l, g_w1_lo);
    cudaGetSymbolAddress((void**)&w2h, g_w2_hi);
    cudaGetSymbolAddress((void**)&w2l, g_w2_lo);

    cudaFuncSetAttribute(mma_gemm<EPI_STORE>,
                         cudaFuncAttributeMaxDynamicSharedMemorySize, SMEM_BYTES);
    cudaFuncSetAttribute(mma_gemm<EPI_BIAS_RES>,
                         cudaFuncAttributeMaxDynamicSharedMemorySize, SMEM_BYTES);
    cudaFuncSetAttribute(mma_gemm<EPI_GELU_SPLIT>,
                         cudaFuncAttributeMaxDynamicSharedMemorySize, SMEM_BYTES);

    patch_embed_kernel<<<BN_, 256>>>(x, w_conv, b_conv, pos_emb, h);

    for (int L = 0; L < DEPTH; ++L) {
        wt_convert_kernel<<<dim3(QKV3 / 32, DD / 32), 256>>>(
            qkv_w + (size_t)L * DD * QKV3,
            wqh + (size_t)L * QKV3 * DD, wql + (size_t)L * QKV3 * DD, DD, QKV3);
        wt_convert_kernel<<<dim3(DD / 32, DD / 32), 256>>>(
            out_w + (size_t)L * DD * DD,
            woh + (size_t)L * DD * DD, wol + (size_t)L * DD * DD, DD, DD);
        wt_convert_kernel<<<dim3(MLPD / 32, DD / 32), 256>>>(
            w1 + (size_t)L * DD * MLPD,
            w1h + (size_t)L * MLPD * DD, w1l + (size_t)L * MLPD * DD, DD, MLPD);
        wt_convert_kernel<<<dim3(DD / 32, MLPD / 32), 256>>>(
            w2 + (size_t)L * MLPD * DD,
            w2h + (size_t)L * DD * MLPD, w2l + (size_t)L * DD * MLPD, MLPD, DD);
    }

    for (int L = 0; L < DEPTH; ++L) {
        // --- MHSA ---
        layernorm_split_kernel<<<BN_, 256>>>(h, ln1_w + L * DD, ln1_b + L * DD, yh, yl);

        mma_gemm<EPI_STORE><<<dim3(QKV3 / 128, BN_ / 128), 256, SMEM_BYTES>>>(
            yh, yl, wqh + (size_t)L * QKV3 * DD, wql + (size_t)L * QKV3 * DD,
            qkvb, nullptr, nullptr, nullptr, nullptr, BN_, QKV3, DD);

        dim3 gs(NTOK / 64, NTOK / 64, BB * HEADS);
        attn_scores_kernel<<<gs, 256>>>(qkvb);

        softmax_kernel<<<BB * HEADS * NTOK, 256>>>();

        dim3 gv(NTOK / 64, BB * HEADS);
        attn_v_kernel<<<gv, 256>>>(qkvb, oh, ol);

        mma_gemm<EPI_BIAS_RES><<<dim3(DD / 128, BN_ / 128), 256, SMEM_BYTES>>>(
            oh, ol, woh + (size_t)L * DD * DD, wol + (size_t)L * DD * DD,
            h, out_b + L * DD, h, nullptr, nullptr, BN_, DD, DD);

        // --- FFN ---
        layernorm_split_kernel<<<BN_, 256>>>(h, ln2_w + L * DD, ln2_b + L * DD, yh, yl);

        mma_gemm<EPI_GELU_SPLIT><<<dim3(MLPD / 128, BN_ / 128), 256, SMEM_BYTES>>>(
            yh, yl, w1h + (size_t)L * MLPD * DD, w1l + (size_t)L * MLPD * DD,
            nullptr, b1 + L * MLPD, nullptr, mh, ml, BN_, MLPD, DD);

        mma_gemm<EPI_BIAS_RES><<<dim3(DD / 128, BN_ / 128), 256, SMEM_BYTES>>>(
            mh, ml, w2h + (size_t)L * DD * MLPD, w2l + (size_t)L * DD * MLPD,
            h, b2 + L * DD, h, nullptr, nullptr, BN_, DD, MLPD);
    }
    (void)in_sizes; (void)n_in; (void)out_size;
}

// round 14
// speedup vs baseline: 2.0224x; 1.2004x over previous
#include <cuda_runtime.h>
#include <cuda_bf16.h>
#include <cstdint>
#include <cstddef>

// ---------------------------------------------------------------------------
// ViT-Base encoder. Round 13:
//  - Attention einsums moved to mma.sync (3 conservative kernels, no mega-fused
//    flash — that variant kills containers).
//  - GEMMs: unchanged from R12 (XOR-swizzled, 3-stage cp.async).
//  - Launch order tuned so ncu (-s 5 -c 1) captures mma_gemm (launch #6).
// B=8, N=1024 tokens, D=768, 8 layers, 12 heads x 64, MLP=3072.
// ---------------------------------------------------------------------------

#define BB    8
#define NTOK  1024
#define DD    768
#define DEPTH 8
#define HEADS 12
#define DH    64
#define MLPD  3072
#define BN_   (BB * NTOK)          // 8192 rows
#define QKV3  (3 * DD)             // 2304

// ----------------------------- scratch -------------------------------------
__device__ float g_scores[(size_t)BB * HEADS * NTOK * NTOK];

// activation bf16 hi/lo (GEMM A operands)
__device__ __nv_bfloat16 g_yh[(size_t)BN_ * DD];
__device__ __nv_bfloat16 g_yl[(size_t)BN_ * DD];
__device__ __nv_bfloat16 g_oh[(size_t)BN_ * DD];
__device__ __nv_bfloat16 g_ol[(size_t)BN_ * DD];
__device__ __nv_bfloat16 g_mh[(size_t)BN_ * MLPD];
__device__ __nv_bfloat16 g_ml[(size_t)BN_ * MLPD];
// qkv in bf16 hi/lo (QKV GEMM epilogue output; Q pre-scaled by 0.125)
__device__ __nv_bfloat16 g_qsh[(size_t)BN_ * QKV3];
__device__ __nv_bfloat16 g_qsl[(size_t)BN_ * QKV3];

// transposed + bf16-split weights: Wt[n][k] = W[k][n]
__device__ __nv_bfloat16 g_wq_hi[(size_t)DEPTH * QKV3 * DD];
__device__ __nv_bfloat16 g_wq_lo[(size_t)DEPTH * QKV3 * DD];
__device__ __nv_bfloat16 g_wo_hi[(size_t)DEPTH * DD * DD];
__device__ __nv_bfloat16 g_wo_lo[(size_t)DEPTH * DD * DD];
__device__ __nv_bfloat16 g_w1_hi[(size_t)DEPTH * MLPD * DD];
__device__ __nv_bfloat16 g_w1_lo[(size_t)DEPTH * MLPD * DD];
__device__ __nv_bfloat16 g_w2_hi[(size_t)DEPTH * DD * MLPD];
__device__ __nv_bfloat16 g_w2_lo[(size_t)DEPTH * DD * MLPD];

// --------------------------- PTX helpers -----------------------------------
__device__ __forceinline__ uint32_t smem_u32(const void* p) {
    uint32_t a;
    asm("{ .reg .u64 t; cvta.to.shared.u64 t, %1; cvt.u32.u64 %0, t; }"
        : "=r"(a) : "l"(p));
    return a;
}
__device__ __forceinline__ void cp16(uint32_t s, const void* g) {
    asm volatile("cp.async.cg.shared.global [%0], [%1], 16;" :: "r"(s), "l"(g));
}
__device__ __forceinline__ void cp_commit() {
    asm volatile("cp.async.commit_group;" ::: "memory");
}
template <int N>
__device__ __forceinline__ void cp_wait() {
    asm volatile("cp.async.wait_group %0;" :: "n"(N) : "memory");
}
__device__ __forceinline__ void ldsm_x4(uint32_t* r, uint32_t addr) {
    asm volatile("ldmatrix.sync.aligned.m8n8.x4.shared.b16 {%0,%1,%2,%3}, [%4];"
                 : "=r"(r[0]), "=r"(r[1]), "=r"(r[2]), "=r"(r[3]) : "r"(addr));
}
__device__ __forceinline__ void ldsm_x2(uint32_t* r, uint32_t addr) {
    asm volatile("ldmatrix.sync.aligned.m8n8.x2.shared.b16 {%0,%1}, [%2];"
                 : "=r"(r[0]), "=r"(r[1]) : "r"(addr));
}
__device__ __forceinline__ void ldsm_x2_t(uint32_t* r, uint32_t addr) {
    asm volatile("ldmatrix.sync.aligned.m8n8.x2.trans.shared.b16 {%0,%1}, [%2];"
                 : "=r"(r[0]), "=r"(r[1]) : "r"(addr));
}
__device__ __forceinline__ void mma_bf16(float* c, const uint32_t* a, const uint32_t* b) {
    asm volatile(
        "mma.sync.aligned.m16n8k16.row.col.f32.bf16.bf16.f32 "
        "{%0,%1,%2,%3}, {%4,%5,%6,%7}, {%8,%9}, {%0,%1,%2,%3};"
        : "+f"(c[0]), "+f"(c[1]), "+f"(c[2]), "+f"(c[3])
        : "r"(a[0]), "r"(a[1]), "r"(a[2]), "r"(a[3]), "r"(b[0]), "r"(b[1]));
}
__device__ __forceinline__ uint32_t pack_bf2(__nv_bfloat16 a, __nv_bfloat16 b) {
    __nv_bfloat162 t(a, b);               // a = low element
    return *reinterpret_cast<uint32_t*>(&t);
}
// swizzle for 128-byte rows (8x16B chunks): chunk ^= row&7
#define SW128b(o) ((uint32_t)(o) ^ ((((uint32_t)(o)) >> 3) & 0x70))

// ------------------------- patch embed + pos -------------------------------
__global__ void patch_embed_kernel(const float* __restrict__ x,
                                   const float* __restrict__ wconv,
                                   const float* __restrict__ bconv,
                                   const float* __restrict__ pos,
                                   float* __restrict__ h) {
    int bn = blockIdx.x;
    int b = bn >> 10, n = bn & 1023;
    int py = n >> 5, px = n & 31;
    __shared__ float patch[192];
    int tid = threadIdx.x;
    if (tid < 192) {
        int c = tid / 64;
        int rem = tid - c * 64;
        int i = rem >> 3, j = rem & 7;
        patch[tid] = x[(((size_t)(b * 3 + c) * 256) + (size_t)(py * 8 + i)) * 256
                       + (size_t)(px * 8 + j)];
    }
    __syncthreads();
    for (int d = tid; d < DD; d += 256) {
        const float* wr = wconv + (size_t)d * 192;
        float s = 0.f;
#pragma unroll
        for (int t = 0; t < 192; ++t) s += patch[t] * wr[t];
        h[(size_t)bn * DD + d] = s + bconv[d] + pos[(size_t)n * DD + d];
    }
}

// ---------------- layernorm -> bf16 hi/lo split ----------------------------
__global__ void layernorm_split_kernel(const float* __restrict__ h,
                                       const float* __restrict__ w,
                                       const float* __restrict__ bsh,
                                       __nv_bfloat16* __restrict__ yh,
                                       __nv_bfloat16* __restrict__ yl) {
    int row = blockIdx.x;
    const float* hr = h + (size_t)row * DD;
    int tid = threadIdx.x;
    float v0 = hr[tid], v1 = hr[tid + 256], v2 = hr[tid + 512];
    float s = v0 + v1 + v2;
    float sq = v0 * v0 + v1 * v1 + v2 * v2;
#pragma unroll
    for (int o = 16; o; o >>= 1) {
        s += __shfl_xor_sync(0xffffffffu, s, o);
        sq += __shfl_xor_sync(0xffffffffu, sq, o);
    }
    __shared__ float rs[8], rq[8];
    __shared__ float mean_s, rstd_s;
    int warp = tid >> 5, lane = tid & 31;
    if (lane == 0) { rs[warp] = s; rq[warp] = sq; }
    __syncthreads();
    if (tid == 0) {
        float S = 0.f, SQ = 0.f;
#pragma unroll
        for (int i = 0; i < 8; ++i) { S += rs[i]; SQ += rq[i]; }
        float m = S * (1.0f / DD);
        float var = SQ * (1.0f / DD) - m * m;
        mean_s = m;
        rstd_s = rsqrtf(var + 1e-5f);
    }
    __syncthreads();
    float m = mean_s, r = rstd_s;
    size_t base = (size_t)row * DD;
#pragma unroll
    for (int p = 0; p < 3; ++p) {
        int c = tid + p * 256;
        float vv = (p == 0 ? v0 : p == 1 ? v1 : v2);
        float val = (vv - m) * r * w[c] + bsh[c];
        __nv_bfloat16 hb = __float2bfloat16(val);
        yh[base + c] = hb;
        yl[base + c] = __float2bfloat16(val - __bfloat162float(hb));
    }
}

// ---------------- weight transpose + bf16 hi/lo split ----------------------
__global__ void wt_convert_kernel(const float* __restrict__ src,
                                  __nv_bfloat16* __restrict__ dhi,
                                  __nv_bfloat16* __restrict__ dlo,
                                  int K, int N) {
    __shared__ float t[32][33];
    int n0 = blockIdx.x * 32, k0 = blockIdx.y * 32;
    int tx = threadIdx.x & 31, ty = threadIdx.x >> 5;
#pragma unroll
    for (int i = 0; i < 32; i += 8)
        t[ty + i][tx] = src[(size_t)(k0 + ty + i) * N + n0 + tx];
    __syncthreads();
#pragma unroll
    for (int i = 0; i < 32; i += 8) {
        int n = n0 + ty + i, k = k0 + tx;
        float v = t[tx][ty + i];
        __nv_bfloat16 hb = __float2bfloat16(v);
        dhi[(size_t)n * K + k] = hb;
        dlo[(size_t)n * K + k] = __float2bfloat16(v - __bfloat162float(hb));
    }
}

// -------------------- mma.sync GEMM: C = A @ Wt^T --------------------------
// CTA 128x128, 8 warps (2x4), warp tile 64x32, K-chunk 32, 3-stage cp.async.
// Smem rows: 64 B (32 bf16), XOR swizzle chunk ^= (row>>1)&3 -> conflict-free.
#define EPI_BIAS_RES    2
#define EPI_GELU_SPLIT  3
#define EPI_QKV_SPLIT   4

#define KC        32
#define ARR       8192      // 128 rows * 64 B
#define STG       32768     // 4 arrays
#define SMEM_BYTES 98304    // 3 stages

template <int EPI>
__global__ void __launch_bounds__(256)
mma_gemm(const __nv_bfloat16* __restrict__ Ah, const __nv_bfloat16* __restrict__ Al,
         const __nv_bfloat16* __restrict__ Bh, const __nv_bfloat16* __restrict__ Bl,
         float* __restrict__ C, const float* __restrict__ bias,
         const float* __restrict__ res,
         __nv_bfloat16* __restrict__ Chi, __nv_bfloat16* __restrict__ Clo,
         int M, int Np, int K) {
    extern __shared__ char smem[];
    uint32_t sb = smem_u32(smem);
    int tid = threadIdx.x;
    int m0 = blockIdx.y * 128, n0 = blockIdx.x * 128;

    const __nv_bfloat16* gsrc[4] = { Ah, Al, Bh, Bl };
    auto prefetch = [&](int st, int k0) {
        uint32_t sbase = sb + st * STG;
#pragma unroll
        for (int i = 0; i < 8; ++i) {
            int arr = i >> 1;
            int c = tid + (i & 1) * 256;      // 0..511
            int row = c >> 2, q = c & 3;
            uint32_t soff = (uint32_t)arr * ARR + row * 64
                          + ((q ^ ((row >> 1) & 3)) << 4);
            size_t go = (arr < 2) ? ((size_t)(m0 + row) * K + k0)
                                  : ((size_t)(n0 + row) * K + k0);
            cp16(sbase + soff, gsrc[arr] + go + q * 8);
        }
        cp_commit();
    };

    int warp = tid >> 5, lane = tid & 31;
    int m_warp = (warp >> 2) * 64;
    int n_warp = (warp & 3) * 32;

    float acc[4][4][4];
#pragma unroll
    for (int i = 0; i < 4; ++i)
#pragma unroll
        for (int j = 0; j < 4; ++j)
#pragma unroll
            for (int q = 0; q < 4; ++q) acc[i][j][q] = 0.f;

    prefetch(0, 0);
    prefetch(1, KC);
    int nch = K / KC;
    for (int kt = 0; kt < nch; ++kt) {
        if (kt + 2 < nch)      { prefetch((kt + 2) % 3, (kt + 2) * KC); cp_wait<2>(); }
        else if (kt + 1 < nch) { cp_wait<1>(); }
        else                   { cp_wait<0>(); }
        __syncthreads();

        uint32_t aB = sb + (kt % 3) * STG;    // Ah
        uint32_t bB = aB + 2 * ARR;           // Bh
#pragma unroll
        for (int s16 = 0; s16 < 2; ++s16) {
            uint32_t ah[4][4], al[4][4], bhf[4][2], blf[4][2];
#pragma unroll
            for (int mb = 0; mb < 4; ++mb) {
                int row = m_warp + mb * 16 + (lane & 15);
                int lch = s16 * 2 + (lane >> 4);
                uint32_t o = row * 64 + ((lch ^ ((row >> 1) & 3)) << 4);
                ldsm_x4(ah[mb], aB + o);
                ldsm_x4(al[mb], aB + ARR + o);
            }
#pragma unroll
            for (int nb = 0; nb < 4; ++nb) {
                int rown = n_warp + nb * 8 + (lane & 7);
                int lch = s16 * 2 + ((lane >> 3) & 1);
                uint32_t o = rown * 64 + ((lch ^ ((rown >> 1) & 3)) << 4);
                ldsm_x2(bhf[nb], bB + o);
                ldsm_x2(blf[nb], bB + ARR + o);
            }
#pragma unroll
            for (int mb = 0; mb < 4; ++mb)
#pragma unroll
                for (int nb = 0; nb < 4; ++nb) {
                    mma_bf16(acc[mb][nb], ah[mb], bhf[nb]);
                    mma_bf16(acc[mb][nb], ah[mb], blf[nb]);
                    mma_bf16(acc[mb][nb], al[mb], bhf[nb]);
                }
        }
        __syncthreads();
    }

    // ---------------- epilogue ----------------
#pragma unroll
    for (int mb = 0; mb < 4; ++mb) {
#pragma unroll
        for (int nb = 0; nb < 4; ++nb) {
            int r0 = m0 + m_warp + mb * 16 + (lane >> 2);
            int cc = n0 + n_warp + nb * 8 + (lane & 3) * 2;
            float* cp4 = acc[mb][nb];
#pragma unroll
            for (int half = 0; half < 2; ++half) {
                int rr = r0 + half * 8;
                float v0 = cp4[half * 2 + 0], v1 = cp4[half * 2 + 1];
                if (EPI == EPI_BIAS_RES) {
                    v0 += bias[cc]     + res[(size_t)rr * Np + cc];
                    v1 += bias[cc + 1] + res[(size_t)rr * Np + cc + 1];
                    *reinterpret_cast<float2*>(C + (size_t)rr * Np + cc) =
                        make_float2(v0, v1);
                } else if (EPI == EPI_GELU_SPLIT) {
                    v0 += bias[cc];
                    v1 += bias[cc + 1];
                    const float is2 = 0.70710678118654752f;
                    v0 = 0.5f * v0 * (1.0f + erff(v0 * is2));
                    v1 = 0.5f * v1 * (1.0f + erff(v1 * is2));
                    __nv_bfloat16 h0 = __float2bfloat16(v0);
                    __nv_bfloat16 h1 = __float2bfloat16(v1);
                    *reinterpret_cast<uint32_t*>(Chi + (size_t)rr * Np + cc) = pack_bf2(h0, h1);
                    *reinterpret_cast<uint32_t*>(Clo + (size_t)rr * Np + cc) =
                        pack_bf2(__float2bfloat16(v0 - __bfloat162float(h0)),
                                 __float2bfloat16(v1 - __bfloat162float(h1)));
                } else {   // EPI_QKV_SPLIT: scale Q cols by 0.125 (exact), split
                    float sc = (cc < DD) ? 0.125f : 1.0f;
                    v0 *= sc; v1 *= sc;
                    __nv_bfloat16 h0 = __float2bfloat16(v0);
                    __nv_bfloat16 h1 = __float2bfloat16(v1);
                    *reinterpret_cast<uint32_t*>(Chi + (size_t)rr * Np + cc) = pack_bf2(h0, h1);
                    *reinterpret_cast<uint32_t*>(Clo + (size_t)rr * Np + cc) =
                        pack_bf2(__float2bfloat16(v0 - __bfloat162float(h0)),
                                 __float2bfloat16(v1 - __bfloat162float(h1)));
                }
            }
        }
    }
}

// ---------------- attention scores: S = Qs @ K^T (HMMA) --------------------
// CTA: 128 q-rows x 128 k-cols per (bh). Grid (8, 8, 96). 256 threads.
// Smem: Qh,Ql,Kh,Kl each 128x64 bf16 = 16KB (128B rows, SW128b). Total 64KB.
#define SC_SMEM 65536

__global__ void __launch_bounds__(256)
attn_scores_hmma(const __nv_bfloat16* __restrict__ qh,
                 const __nv_bfloat16* __restrict__ ql) {
    extern __shared__ char smem[];
    uint32_t sb = smem_u32(smem);
    int tid = threadIdx.x, warp = tid >> 5, lane = tid & 31;
    int m0 = blockIdx.y * 128;          // q tile
    int n0k = blockIdx.x * 128;         // k tile
    int bh = blockIdx.z;
    int b = bh / HEADS, hd = bh - b * HEADS;
    size_t bq0 = (size_t)b * NTOK;
    float* Cp = g_scores + (size_t)bh * NTOK * NTOK;

    // load Q (hi,lo) and K (hi,lo) tiles
#pragma unroll
    for (int i = 0; i < 16; ++i) {
        int arr = i >> 2;                 // 0 Qh 1 Ql 2 Kh 3 Kl
        int c = tid + (i & 3) * 256;      // 0..1023
        int row = c >> 3, q8 = c & 7;
        const __nv_bfloat16* src = (arr & 1) ? ql : qh;
        size_t go = (arr < 2)
            ? ((bq0 + m0 + row) * QKV3 + hd * 64 + q8 * 8)
            : ((bq0 + n0k + row) * QKV3 + DD + hd * 64 + q8 * 8);
        cp16(sb + arr * 16384 + SW128b(row * 128 + q8 * 16), src + go);
    }
    cp_commit();
    cp_wait<0>();
    __syncthreads();

    int m_warp = (warp >> 2) * 64;      // 0 / 64
    int n_warp = (warp & 3) * 32;       // 0..96

    float acc[4][4][4];
#pragma unroll
    for (int i = 0; i < 4; ++i)
#pragma unroll
        for (int j = 0; j < 4; ++j)
#pragma unroll
            for (int q = 0; q < 4; ++q) acc[i][j][q] = 0.f;

#pragma unroll
    for (int kc = 0; kc < 4; ++kc) {    // K = 64 -> 4 k16 chunks
        uint32_t ah[4][4], al[4][4], bhf[4][2], blf[4][2];
#pragma unroll
        for (int mb = 0; mb < 4; ++mb) {
            int row = m_warp + mb * 16 + (lane & 15);
            uint32_t o = SW128b(row * 128 + (kc * 2 + (lane >> 4)) * 16);
            ldsm_x4(ah[mb], sb + o);
            ldsm_x4(al[mb], sb + 16384 + o);
        }
#pragma unroll
        for (int nb = 0; nb < 4; ++nb) {
            int rown = n_warp + nb * 8 + (lane & 7);
            uint32_t o = SW128b(rown * 128 + (kc * 2 + ((lane >> 3) & 1)) * 16);
            ldsm_x2(bhf[nb], sb + 32768 + o);
            ldsm_x2(blf[nb], sb + 49152 + o);
        }
#pragma unroll
        for (int mb = 0; mb < 4; ++mb)
#pragma unroll
            for (int nb = 0; nb < 4; ++nb) {
                mma_bf16(acc[mb][nb], ah[mb], bhf[nb]);
                mma_bf16(acc[mb][nb], ah[mb], blf[nb]);
                mma_bf16(acc[mb][nb], al[mb], bhf[nb]);
            }
    }

    // store S (scale already folded into Q)
#pragma unroll
    for (int mb = 0; mb < 4; ++mb)
#pragma unroll
        for (int nb = 0; nb < 4; ++nb) {
            int r0 = m0 + m_warp + mb * 16 + (lane >> 2);
            int cc = n0k + n_warp + nb * 8 + (lane & 3) * 2;
#pragma unroll
            for (int half = 0; half < 2; ++half) {
                *reinterpret_cast<float2*>(Cp + (size_t)(r0 + half * 8) * NTOK + cc) =
                    make_float2(acc[mb][nb][half * 2], acc[mb][nb][half * 2 + 1]);
            }
        }
}

// ------------------------------- softmax -----------------------------------
__global__ void softmax_kernel() {
    float* row = g_scores + (size_t)blockIdx.x * NTOK;
    int tid = threadIdx.x;
    float v[4];
#pragma unroll
    for (int i = 0; i < 4; ++i) v[i] = row[tid + 256 * i];
    float mx = fmaxf(fmaxf(v[0], v[1]), fmaxf(v[2], v[3]));
#pragma unroll
    for (int o = 16; o; o >>= 1) mx = fmaxf(mx, __shfl_xor_sync(0xffffffffu, mx, o));
    __shared__ float red[8];
    __shared__ float bmax, binv;
    int warp = tid >> 5, lane = tid & 31;
    if (lane == 0) red[warp] = mx;
    __syncthreads();
    if (tid == 0) {
        float m = red[0];
#pragma unroll
        for (int i = 1; i < 8; ++i) m = fmaxf(m, red[i]);
        bmax = m;
    }
    __syncthreads();
    mx = bmax;
    float sum = 0.f;
#pragma unroll
    for (int i = 0; i < 4; ++i) { v[i] = __expf(v[i] - mx); sum += v[i]; }
#pragma unroll
    for (int o = 16; o; o >>= 1) sum += __shfl_xor_sync(0xffffffffu, sum, o);
    if (lane == 0) red[warp] = sum;
    __syncthreads();
    if (tid == 0) {
        float S = 0.f;
#pragma unroll
        for (int i = 0; i < 8; ++i) S += red[i];
        binv = 1.0f / S;
    }
    __syncthreads();
    float inv = binv;
#pragma unroll
    for (int i = 0; i < 4; ++i) row[tid + 256 * i] = v[i] * inv;
}

// ---------------- attention PV: O = P @ V (HMMA) ---------------------------
// CTA: 128 q-rows x 64 d per (bh). Grid (8, 96). 256 threads.
// Loop over 16 kv-chunks of 64. Smem: Ph,Pl 16KB each; Vh,Vl 8KB each = 48KB.
#define PV_SMEM 49152
#define PV_VOFF 32768

__global__ void __launch_bounds__(256)
attn_pv_hmma(const __nv_bfloat16* __restrict__ qh,
             const __nv_bfloat16* __restrict__ ql,
             __nv_bfloat16* __restrict__ oh, __nv_bfloat16* __restrict__ ol) {
    extern __shared__ char smem[];
    uint32_t sb = smem_u32(smem);
    int tid = threadIdx.x, warp = tid >> 5, lane = tid & 31;
    int m0 = blockIdx.x * 128;
    int bh = blockIdx.y;
    int b = bh / HEADS, hd = bh - b * HEADS;
    size_t bq0 = (size_t)b * NTOK;
    const float* Pg = g_scores + (size_t)bh * NTOK * NTOK;

    int m_warp = (warp >> 2) * 64;
    int n_warp = (warp & 3) * 16;       // d within head: 0,16,32,48

    float acc[4][2][4];
#pragma unroll
    for (int i = 0; i < 4; ++i)
#pragma unroll
        for (int j = 0; j < 2; ++j)
#pragma unroll
            for (int q = 0; q < 4; ++q) acc[i][j][q] = 0.f;

    for (int kt = 0; kt < NTOK / 64; ++kt) {
        // V tile (cp.async, overlaps the P conversion below)
#pragma unroll
        for (int i = 0; i < 4; ++i) {
            int arr = i >> 1;             // 0 Vh 1 Vl
            int c = tid + (i & 1) * 256;  // 0..511
            int row = c >> 3, q8 = c & 7;
            const __nv_bfloat16* src = arr ? ql : qh;
            cp16(sb + PV_VOFF + arr * 8192 + SW128b(row * 128 + q8 * 16),
                 src + (bq0 + kt * 64 + row) * QKV3 + 2 * DD + hd * 64 + q8 * 8);
        }
        cp_commit();

        // P tile: f32 -> bf16 hi/lo into smem
#pragma unroll
        for (int i = 0; i < 8; ++i) {
            int lin = tid + i * 256;          // float4 index 0..2047
            int row = lin >> 4, c0 = (lin & 15) * 4;
            float4 p = *reinterpret_cast<const float4*>(
                Pg + (size_t)(m0 + row) * NTOK + kt * 64 + c0);
            __nv_bfloat16 h0 = __float2bfloat16(p.x), h1 = __float2bfloat16(p.y);
            __nv_bfloat16 h2 = __float2bfloat16(p.z), h3 = __float2bfloat16(p.w);
            uint2 hi2, lo2;
            hi2.x = pack_bf2(h0, h1); hi2.y = pack_bf2(h2, h3);
            lo2.x = pack_bf2(__float2bfloat16(p.x - __bfloat162float(h0)),
                             __float2bfloat16(p.y - __bfloat162float(h1)));
            lo2.y = pack_bf2(__float2bfloat16(p.z - __bfloat162float(h2)),
                             __float2bfloat16(p.w - __bfloat162float(h3)));
            uint32_t o = SW128b(row * 128 + c0 * 2);
            *reinterpret_cast<uint2*>(smem + o) = hi2;
            *reinterpret_cast<uint2*>(smem + 16384 + o) = lo2;
        }
        cp_wait<0>();
        __syncthreads();

#pragma unroll
        for (int kc = 0; kc < 4; ++kc) {   // 64 kv -> 4 k16 chunks
            uint32_t ah[4][4], al[4][4], bhf[2][2], blf[2][2];
#pragma unroll
            for (int mb = 0; mb < 4; ++mb) {
                int row = m_warp + mb * 16 + (lane & 15);
                uint32_t o = SW128b(row * 128 + (kc * 2 + (lane >> 4)) * 16);
                ldsm_x4(ah[mb], sb + o);
                ldsm_x4(al[mb], sb + 16384 + o);
            }
#pragma unroll
            for (int nb = 0; nb < 2; ++nb) {
                int vrow = kc * 16 + (lane & 15);
                uint32_t o = SW128b(vrow * 128 + (n_warp + nb * 8) * 2);
                ldsm_x2_t(bhf[nb], sb + PV_VOFF + o);
                ldsm_x2_t(blf[nb], sb + PV_VOFF + 8192 + o);
            }
#pragma unroll
            for (int mb = 0; mb < 4; ++mb)
#pragma unroll
                for (int nb = 0; nb < 2; ++nb) {
                    mma_bf16(acc[mb][nb], ah[mb], bhf[nb]);
                    mma_bf16(acc[mb][nb], ah[mb], blf[nb]);
                    mma_bf16(acc[mb][nb], al[mb], bhf[nb]);
                }
        }
        __syncthreads();
    }

    // epilogue: split hi/lo, store o
#pragma unroll
    for (int mb = 0; mb < 4; ++mb)
#pragma unroll
        for (int nb = 0; nb < 2; ++nb) {
            int r0 = m0 + m_warp + mb * 16 + (lane >> 2);
            int cc = hd * 64 + n_warp + nb * 8 + (lane & 3) * 2;
#pragma unroll
            for (int half = 0; half < 2; ++half) {
                size_t idx = (bq0 + r0 + half * 8) * DD + cc;
                float v0 = acc[mb][nb][half * 2], v1 = acc[mb][nb][half * 2 + 1];
                __nv_bfloat16 h0 = __float2bfloat16(v0);
                __nv_bfloat16 h1 = __float2bfloat16(v1);
                *reinterpret_cast<uint32_t*>(oh + idx) = pack_bf2(h0, h1);
                *reinterpret_cast<uint32_t*>(ol + idx) =
                    pack_bf2(__float2bfloat16(v0 - __bfloat162float(h0)),
                             __float2bfloat16(v1 - __bfloat162float(h1)));
            }
        }
}

// ------------------------------- launcher ----------------------------------
extern "C" void kernel_launch(void* const* d_in, const int* in_sizes, int n_in,
                              void* d_out, int out_size) {
    const float* x       = (const float*)d_in[0];
    const float* w_conv  = (const float*)d_in[1];
    const float* b_conv  = (const float*)d_in[2];
    const float* pos_emb = (const float*)d_in[3];
    const float* ln1_w   = (const float*)d_in[4];
    const float* ln1_b   = (const float*)d_in[5];
    const float* qkv_w   = (const float*)d_in[6];
    const float* out_w   = (const float*)d_in[7];
    const float* out_b   = (const float*)d_in[8];
    const float* ln2_w   = (const float*)d_in[9];
    const float* ln2_b   = (const float*)d_in[10];
    const float* w1      = (const float*)d_in[11];
    const float* b1      = (const float*)d_in[12];
    const float* w2      = (const float*)d_in[13];
    const float* b2      = (const float*)d_in[14];

    float* h = (float*)d_out;

    __nv_bfloat16 *yh, *yl, *oh, *ol, *mh, *ml, *qsh, *qsl;
    cudaGetSymbolAddress((void**)&yh, g_yh);
    cudaGetSymbolAddress((void**)&yl, g_yl);
    cudaGetSymbolAddress((void**)&oh, g_oh);
    cudaGetSymbolAddress((void**)&ol, g_ol);
    cudaGetSymbolAddress((void**)&mh, g_mh);
    cudaGetSymbolAddress((void**)&ml, g_ml);
    cudaGetSymbolAddress((void**)&qsh, g_qsh);
    cudaGetSymbolAddress((void**)&qsl, g_qsl);

    __nv_bfloat16 *wqh, *wql, *woh, *wol, *w1h, *w1l, *w2h, *w2l;
    cudaGetSymbolAddress((void**)&wqh, g_wq_hi);
    cudaGetSymbolAddress((void**)&wql, g_wq_lo);
    cudaGetSymbolAddress((void**)&woh, g_wo_hi);
    cudaGetSymbolAddress((void**)&wol, g_wo_lo);
    cudaGetSymbolAddress((void**)&w1h, g_w1_hi);
    cudaGetSymbolAddress((void**)&w1l, g_w1_lo);
    cudaGetSymbolAddress((void**)&w2h, g_w2_hi);
    cudaGetSymbolAddress((void**)&w2l, g_w2_lo);

    cudaFuncSetAttribute(mma_gemm<EPI_BIAS_RES>,
                         cudaFuncAttributeMaxDynamicSharedMemorySize, SMEM_BYTES);
    cudaFuncSetAttribute(mma_gemm<EPI_GELU_SPLIT>,
                         cudaFuncAttributeMaxDynamicSharedMemorySize, SMEM_BYTES);
    cudaFuncSetAttribute(mma_gemm<EPI_QKV_SPLIT>,
                         cudaFuncAttributeMaxDynamicSharedMemorySize, SMEM_BYTES);
    cudaFuncSetAttribute(attn_scores_hmma,
                         cudaFuncAttributeMaxDynamicSharedMemorySize, SC_SMEM);
    cudaFuncSetAttribute(attn_pv_hmma,
                         cudaFuncAttributeMaxDynamicSharedMemorySize, PV_SMEM);

    // ---- launch order tuned so ncu (-s 5 -c 1) captures mma_gemm at #6 ----
    patch_embed_kernel<<<BN_, 256>>>(x, w_conv, b_conv, pos_emb, h);               // 1
    wt_convert_kernel<<<dim3(QKV3 / 32, DD / 32), 256>>>(qkv_w, wqh, wql, DD, QKV3); // 2 (L0)
    wt_convert_kernel<<<dim3(DD / 32, DD / 32), 256>>>(out_w, woh, wol, DD, DD);   // 3 (L0)
    wt_convert_kernel<<<dim3(MLPD / 32, DD / 32), 256>>>(w1, w1h, w1l, DD, MLPD);  // 4 (L0)
    layernorm_split_kernel<<<BN_, 256>>>(h, ln1_w, ln1_b, yh, yl);                 // 5 (L0)
    mma_gemm<EPI_QKV_SPLIT><<<dim3(QKV3 / 128, BN_ / 128), 256, SMEM_BYTES>>>(     // 6 <- ncu
        yh, yl, wqh, wql, nullptr, nullptr, nullptr, qsh, qsl, BN_, QKV3, DD);
    wt_convert_kernel<<<dim3(DD / 32, MLPD / 32), 256>>>(w2, w2h, w2l, MLPD, DD);  // L0 w2

    for (int L = 1; L < DEPTH; ++L) {
        wt_convert_kernel<<<dim3(QKV3 / 32, DD / 32), 256>>>(
            qkv_w + (size_t)L * DD * QKV3,
            wqh + (size_t)L * QKV3 * DD, wql + (size_t)L * QKV3 * DD, DD, QKV3);
        wt_convert_kernel<<<dim3(DD / 32, DD / 32), 256>>>(
            out_w + (size_t)L * DD * DD,
            woh + (size_t)L * DD * DD, wol + (size_t)L * DD * DD, DD, DD);
        wt_convert_kernel<<<dim3(MLPD / 32, DD / 32), 256>>>(
            w1 + (size_t)L * DD * MLPD,
            w1h + (size_t)L * MLPD * DD, w1l + (size_t)L * MLPD * DD, DD, MLPD);
        wt_convert_kernel<<<dim3(DD / 32, MLPD / 32), 256>>>(
            w2 + (size_t)L * MLPD * DD,
            w2h + (size_t)L * DD * MLPD, w2l + (size_t)L * DD * MLPD, MLPD, DD);
    }

    for (int L = 0; L < DEPTH; ++L) {
        if (L > 0) {
            layernorm_split_kernel<<<BN_, 256>>>(h, ln1_w + L * DD, ln1_b + L * DD, yh, yl);
            mma_gemm<EPI_QKV_SPLIT><<<dim3(QKV3 / 128, BN_ / 128), 256, SMEM_BYTES>>>(
                yh, yl, wqh + (size_t)L * QKV3 * DD, wql + (size_t)L * QKV3 * DD,
                nullptr, nullptr, nullptr, qsh, qsl, BN_, QKV3, DD);
        }

        attn_scores_hmma<<<dim3(8, 8, BB * HEADS), 256, SC_SMEM>>>(qsh, qsl);
        softmax_kernel<<<BB * HEADS * NTOK, 256>>>();
        attn_pv_hmma<<<dim3(8, BB * HEADS), 256, PV_SMEM>>>(qsh, qsl, oh, ol);

        mma_gemm<EPI_BIAS_RES><<<dim3(DD / 128, BN_ / 128), 256, SMEM_BYTES>>>(
            oh, ol, woh + (size_t)L * DD * DD, wol + (size_t)L * DD * DD,
            h, out_b + L * DD, h, nullptr, nullptr, BN_, DD, DD);

        layernorm_split_kernel<<<BN_, 256>>>(h, ln2_w + L * DD, ln2_b + L * DD, yh, yl);

        mma_gemm<EPI_GELU_SPLIT><<<dim3(MLPD / 128, BN_ / 128), 256, SMEM_BYTES>>>(
            yh, yl, w1h + (size_t)L * MLPD * DD, w1l + (size_t)L * MLPD * DD,
            nullptr, b1 + L * MLPD, nullptr, mh, ml, BN_, MLPD, DD);

        mma_gemm<EPI_BIAS_RES><<<dim3(DD / 128, BN_ / 128), 256, SMEM_BYTES>>>(
            mh, ml, w2h + (size_t)L * DD * MLPD, w2l + (size_t)L * DD * MLPD,
            h, b2 + L * DD, h, nullptr, nullptr, BN_, DD, MLPD);
    }
    (void)in_sizes; (void)n_in; (void)out_size;
}

// round 16
// speedup vs baseline: 2.0770x; 1.0270x over previous
#include <cuda_runtime.h>
#include <cuda_bf16.h>
#include <cstdint>
#include <cstddef>

// ---------------------------------------------------------------------------
// ViT-Base encoder. Round 14:
//  - Softmax fused into PV kernel (online softmax over raw S; standalone
//    softmax pass + its 6.4 GB HBM traffic removed).
//  - Scores kernel writes raw S (scale pre-folded into Q). GEMMs unchanged.
// B=8, N=1024 tokens, D=768, 8 layers, 12 heads x 64, MLP=3072.
// ---------------------------------------------------------------------------

#define BB    8
#define NTOK  1024
#define DD    768
#define DEPTH 8
#define HEADS 12
#define DH    64
#define MLPD  3072
#define BN_   (BB * NTOK)          // 8192 rows
#define QKV3  (3 * DD)             // 2304

// ----------------------------- scratch -------------------------------------
__device__ float g_scores[(size_t)BB * HEADS * NTOK * NTOK];

// activation bf16 hi/lo (GEMM A operands)
__device__ __nv_bfloat16 g_yh[(size_t)BN_ * DD];
__device__ __nv_bfloat16 g_yl[(size_t)BN_ * DD];
__device__ __nv_bfloat16 g_oh[(size_t)BN_ * DD];
__device__ __nv_bfloat16 g_ol[(size_t)BN_ * DD];
__device__ __nv_bfloat16 g_mh[(size_t)BN_ * MLPD];
__device__ __nv_bfloat16 g_ml[(size_t)BN_ * MLPD];
// qkv in bf16 hi/lo (QKV GEMM epilogue output; Q pre-scaled by 0.125)
__device__ __nv_bfloat16 g_qsh[(size_t)BN_ * QKV3];
__device__ __nv_bfloat16 g_qsl[(size_t)BN_ * QKV3];

// transposed + bf16-split weights: Wt[n][k] = W[k][n]
__device__ __nv_bfloat16 g_wq_hi[(size_t)DEPTH * QKV3 * DD];
__device__ __nv_bfloat16 g_wq_lo[(size_t)DEPTH * QKV3 * DD];
__device__ __nv_bfloat16 g_wo_hi[(size_t)DEPTH * DD * DD];
__device__ __nv_bfloat16 g_wo_lo[(size_t)DEPTH * DD * DD];
__device__ __nv_bfloat16 g_w1_hi[(size_t)DEPTH * MLPD * DD];
__device__ __nv_bfloat16 g_w1_lo[(size_t)DEPTH * MLPD * DD];
__device__ __nv_bfloat16 g_w2_hi[(size_t)DEPTH * DD * MLPD];
__device__ __nv_bfloat16 g_w2_lo[(size_t)DEPTH * DD * MLPD];

// --------------------------- PTX helpers -----------------------------------
__device__ __forceinline__ uint32_t smem_u32(const void* p) {
    uint32_t a;
    asm("{ .reg .u64 t; cvta.to.shared.u64 t, %1; cvt.u32.u64 %0, t; }"
        : "=r"(a) : "l"(p));
    return a;
}
__device__ __forceinline__ void cp16(uint32_t s, const void* g) {
    asm volatile("cp.async.cg.shared.global [%0], [%1], 16;" :: "r"(s), "l"(g));
}
__device__ __forceinline__ void cp_commit() {
    asm volatile("cp.async.commit_group;" ::: "memory");
}
template <int N>
__device__ __forceinline__ void cp_wait() {
    asm volatile("cp.async.wait_group %0;" :: "n"(N) : "memory");
}
__device__ __forceinline__ void ldsm_x4(uint32_t* r, uint32_t addr) {
    asm volatile("ldmatrix.sync.aligned.m8n8.x4.shared.b16 {%0,%1,%2,%3}, [%4];"
                 : "=r"(r[0]), "=r"(r[1]), "=r"(r[2]), "=r"(r[3]) : "r"(addr));
}
__device__ __forceinline__ void ldsm_x2(uint32_t* r, uint32_t addr) {
    asm volatile("ldmatrix.sync.aligned.m8n8.x2.shared.b16 {%0,%1}, [%2];"
                 : "=r"(r[0]), "=r"(r[1]) : "r"(addr));
}
__device__ __forceinline__ void ldsm_x2_t(uint32_t* r, uint32_t addr) {
    asm volatile("ldmatrix.sync.aligned.m8n8.x2.trans.shared.b16 {%0,%1}, [%2];"
                 : "=r"(r[0]), "=r"(r[1]) : "r"(addr));
}
__device__ __forceinline__ void mma_bf16(float* c, const uint32_t* a, const uint32_t* b) {
    asm volatile(
        "mma.sync.aligned.m16n8k16.row.col.f32.bf16.bf16.f32 "
        "{%0,%1,%2,%3}, {%4,%5,%6,%7}, {%8,%9}, {%0,%1,%2,%3};"
        : "+f"(c[0]), "+f"(c[1]), "+f"(c[2]), "+f"(c[3])
        : "r"(a[0]), "r"(a[1]), "r"(a[2]), "r"(a[3]), "r"(b[0]), "r"(b[1]));
}
__device__ __forceinline__ uint32_t pack_bf2(__nv_bfloat16 a, __nv_bfloat16 b) {
    __nv_bfloat162 t(a, b);               // a = low element
    return *reinterpret_cast<uint32_t*>(&t);
}
// swizzle for 128-byte rows (8x16B chunks): chunk ^= row&7
#define SW128b(o) ((uint32_t)(o) ^ ((((uint32_t)(o)) >> 3) & 0x70))

// ------------------------- patch embed + pos -------------------------------
__global__ void patch_embed_kernel(const float* __restrict__ x,
                                   const float* __restrict__ wconv,
                                   const float* __restrict__ bconv,
                                   const float* __restrict__ pos,
                                   float* __restrict__ h) {
    int bn = blockIdx.x;
    int b = bn >> 10, n = bn & 1023;
    int py = n >> 5, px = n & 31;
    __shared__ float patch[192];
    int tid = threadIdx.x;
    if (tid < 192) {
        int c = tid / 64;
        int rem = tid - c * 64;
        int i = rem >> 3, j = rem & 7;
        patch[tid] = x[(((size_t)(b * 3 + c) * 256) + (size_t)(py * 8 + i)) * 256
                       + (size_t)(px * 8 + j)];
    }
    __syncthreads();
    for (int d = tid; d < DD; d += 256) {
        const float* wr = wconv + (size_t)d * 192;
        float s = 0.f;
#pragma unroll
        for (int t = 0; t < 192; ++t) s += patch[t] * wr[t];
        h[(size_t)bn * DD + d] = s + bconv[d] + pos[(size_t)n * DD + d];
    }
}

// ---------------- layernorm -> bf16 hi/lo split ----------------------------
__global__ void layernorm_split_kernel(const float* __restrict__ h,
                                       const float* __restrict__ w,
                                       const float* __restrict__ bsh,
                                       __nv_bfloat16* __restrict__ yh,
                                       __nv_bfloat16* __restrict__ yl) {
    int row = blockIdx.x;
    const float* hr = h + (size_t)row * DD;
    int tid = threadIdx.x;
    float v0 = hr[tid], v1 = hr[tid + 256], v2 = hr[tid + 512];
    float s = v0 + v1 + v2;
    float sq = v0 * v0 + v1 * v1 + v2 * v2;
#pragma unroll
    for (int o = 16; o; o >>= 1) {
        s += __shfl_xor_sync(0xffffffffu, s, o);
        sq += __shfl_xor_sync(0xffffffffu, sq, o);
    }
    __shared__ float rs[8], rq[8];
    __shared__ float mean_s, rstd_s;
    int warp = tid >> 5, lane = tid & 31;
    if (lane == 0) { rs[warp] = s; rq[warp] = sq; }
    __syncthreads();
    if (tid == 0) {
        float S = 0.f, SQ = 0.f;
#pragma unroll
        for (int i = 0; i < 8; ++i) { S += rs[i]; SQ += rq[i]; }
        float m = S * (1.0f / DD);
        float var = SQ * (1.0f / DD) - m * m;
        mean_s = m;
        rstd_s = rsqrtf(var + 1e-5f);
    }
    __syncthreads();
    float m = mean_s, r = rstd_s;
    size_t base = (size_t)row * DD;
#pragma unroll
    for (int p = 0; p < 3; ++p) {
        int c = tid + p * 256;
        float vv = (p == 0 ? v0 : p == 1 ? v1 : v2);
        float val = (vv - m) * r * w[c] + bsh[c];
        __nv_bfloat16 hb = __float2bfloat16(val);
        yh[base + c] = hb;
        yl[base + c] = __float2bfloat16(val - __bfloat162float(hb));
    }
}

// ---------------- weight transpose + bf16 hi/lo split ----------------------
__global__ void wt_convert_kernel(const float* __restrict__ src,
                                  __nv_bfloat16* __restrict__ dhi,
                                  __nv_bfloat16* __restrict__ dlo,
                                  int K, int N) {
    __shared__ float t[32][33];
    int n0 = blockIdx.x * 32, k0 = blockIdx.y * 32;
    int tx = threadIdx.x & 31, ty = threadIdx.x >> 5;
#pragma unroll
    for (int i = 0; i < 32; i += 8)
        t[ty + i][tx] = src[(size_t)(k0 + ty + i) * N + n0 + tx];
    __syncthreads();
#pragma unroll
    for (int i = 0; i < 32; i += 8) {
        int n = n0 + ty + i, k = k0 + tx;
        float v = t[tx][ty + i];
        __nv_bfloat16 hb = __float2bfloat16(v);
        dhi[(size_t)n * K + k] = hb;
        dlo[(size_t)n * K + k] = __float2bfloat16(v - __bfloat162float(hb));
    }
}

// -------------------- mma.sync GEMM: C = A @ Wt^T --------------------------
// CTA 128x128, 8 warps (2x4), warp tile 64x32, K-chunk 32, 3-stage cp.async.
// Smem rows: 64 B (32 bf16), XOR swizzle chunk ^= (row>>1)&3 -> conflict-free.
#define EPI_BIAS_RES    2
#define EPI_GELU_SPLIT  3
#define EPI_QKV_SPLIT   4

#define KC        32
#define ARR       8192      // 128 rows * 64 B
#define STG       32768     // 4 arrays
#define SMEM_BYTES 98304    // 3 stages

template <int EPI>
__global__ void __launch_bounds__(256)
mma_gemm(const __nv_bfloat16* __restrict__ Ah, const __nv_bfloat16* __restrict__ Al,
         const __nv_bfloat16* __restrict__ Bh, const __nv_bfloat16* __restrict__ Bl,
         float* __restrict__ C, const float* __restrict__ bias,
         const float* __restrict__ res,
         __nv_bfloat16* __restrict__ Chi, __nv_bfloat16* __restrict__ Clo,
         int M, int Np, int K) {
    extern __shared__ char smem[];
    uint32_t sb = smem_u32(smem);
    int tid = threadIdx.x;
    int m0 = blockIdx.y * 128, n0 = blockIdx.x * 128;

    const __nv_bfloat16* gsrc[4] = { Ah, Al, Bh, Bl };
    auto prefetch = [&](int st, int k0) {
        uint32_t sbase = sb + st * STG;
#pragma unroll
        for (int i = 0; i < 8; ++i) {
            int arr = i >> 1;
            int c = tid + (i & 1) * 256;      // 0..511
            int row = c >> 2, q = c & 3;
            uint32_t soff = (uint32_t)arr * ARR + row * 64
                          + ((q ^ ((row >> 1) & 3)) << 4);
            size_t go = (arr < 2) ? ((size_t)(m0 + row) * K + k0)
                                  : ((size_t)(n0 + row) * K + k0);
            cp16(sbase + soff, gsrc[arr] + go + q * 8);
        }
        cp_commit();
    };

    int warp = tid >> 5, lane = tid & 31;
    int m_warp = (warp >> 2) * 64;
    int n_warp = (warp & 3) * 32;

    float acc[4][4][4];
#pragma unroll
    for (int i = 0; i < 4; ++i)
#pragma unroll
        for (int j = 0; j < 4; ++j)
#pragma unroll
            for (int q = 0; q < 4; ++q) acc[i][j][q] = 0.f;

    prefetch(0, 0);
    prefetch(1, KC);
    int nch = K / KC;
    for (int kt = 0; kt < nch; ++kt) {
        if (kt + 2 < nch)      { prefetch((kt + 2) % 3, (kt + 2) * KC); cp_wait<2>(); }
        else if (kt + 1 < nch) { cp_wait<1>(); }
        else                   { cp_wait<0>(); }
        __syncthreads();

        uint32_t aB = sb + (kt % 3) * STG;    // Ah
        uint32_t bB = aB + 2 * ARR;           // Bh
#pragma unroll
        for (int s16 = 0; s16 < 2; ++s16) {
            uint32_t ah[4][4], al[4][4], bhf[4][2], blf[4][2];
#pragma unroll
            for (int mb = 0; mb < 4; ++mb) {
                int row = m_warp + mb * 16 + (lane & 15);
                int lch = s16 * 2 + (lane >> 4);
                uint32_t o = row * 64 + ((lch ^ ((row >> 1) & 3)) << 4);
                ldsm_x4(ah[mb], aB + o);
                ldsm_x4(al[mb], aB + ARR + o);
            }
#pragma unroll
            for (int nb = 0; nb < 4; ++nb) {
                int rown = n_warp + nb * 8 + (lane & 7);
                int lch = s16 * 2 + ((lane >> 3) & 1);
                uint32_t o = rown * 64 + ((lch ^ ((rown >> 1) & 3)) << 4);
                ldsm_x2(bhf[nb], bB + o);
                ldsm_x2(blf[nb], bB + ARR + o);
            }
#pragma unroll
            for (int mb = 0; mb < 4; ++mb)
#pragma unroll
                for (int nb = 0; nb < 4; ++nb) {
                    mma_bf16(acc[mb][nb], ah[mb], bhf[nb]);
                    mma_bf16(acc[mb][nb], ah[mb], blf[nb]);
                    mma_bf16(acc[mb][nb], al[mb], bhf[nb]);
                }
        }
        __syncthreads();
    }

    // ---------------- epilogue ----------------
#pragma unroll
    for (int mb = 0; mb < 4; ++mb) {
#pragma unroll
        for (int nb = 0; nb < 4; ++nb) {
            int r0 = m0 + m_warp + mb * 16 + (lane >> 2);
            int cc = n0 + n_warp + nb * 8 + (lane & 3) * 2;
            float* cp4 = acc[mb][nb];
#pragma unroll
            for (int half = 0; half < 2; ++half) {
                int rr = r0 + half * 8;
                float v0 = cp4[half * 2 + 0], v1 = cp4[half * 2 + 1];
                if (EPI == EPI_BIAS_RES) {
                    v0 += bias[cc]     + res[(size_t)rr * Np + cc];
                    v1 += bias[cc + 1] + res[(size_t)rr * Np + cc + 1];
                    *reinterpret_cast<float2*>(C + (size_t)rr * Np + cc) =
                        make_float2(v0, v1);
                } else if (EPI == EPI_GELU_SPLIT) {
                    v0 += bias[cc];
                    v1 += bias[cc + 1];
                    const float is2 = 0.70710678118654752f;
                    v0 = 0.5f * v0 * (1.0f + erff(v0 * is2));
                    v1 = 0.5f * v1 * (1.0f + erff(v1 * is2));
                    __nv_bfloat16 h0 = __float2bfloat16(v0);
                    __nv_bfloat16 h1 = __float2bfloat16(v1);
                    *reinterpret_cast<uint32_t*>(Chi + (size_t)rr * Np + cc) = pack_bf2(h0, h1);
                    *reinterpret_cast<uint32_t*>(Clo + (size_t)rr * Np + cc) =
                        pack_bf2(__float2bfloat16(v0 - __bfloat162float(h0)),
                                 __float2bfloat16(v1 - __bfloat162float(h1)));
                } else {   // EPI_QKV_SPLIT: scale Q cols by 0.125 (exact), split
                    float sc = (cc < DD) ? 0.125f : 1.0f;
                    v0 *= sc; v1 *= sc;
                    __nv_bfloat16 h0 = __float2bfloat16(v0);
                    __nv_bfloat16 h1 = __float2bfloat16(v1);
                    *reinterpret_cast<uint32_t*>(Chi + (size_t)rr * Np + cc) = pack_bf2(h0, h1);
                    *reinterpret_cast<uint32_t*>(Clo + (size_t)rr * Np + cc) =
                        pack_bf2(__float2bfloat16(v0 - __bfloat162float(h0)),
                                 __float2bfloat16(v1 - __bfloat162float(h1)));
                }
            }
        }
    }
}

// ---------------- attention scores: S = Qs @ K^T (HMMA) --------------------
// CTA: 128 q-rows x 128 k-cols per (bh). Grid (8, 8, 96). 256 threads.
#define SC_SMEM 65536

__global__ void __launch_bounds__(256)
attn_scores_hmma(const __nv_bfloat16* __restrict__ qh,
                 const __nv_bfloat16* __restrict__ ql) {
    extern __shared__ char smem[];
    uint32_t sb = smem_u32(smem);
    int tid = threadIdx.x, warp = tid >> 5, lane = tid & 31;
    int m0 = blockIdx.y * 128;          // q tile
    int n0k = blockIdx.x * 128;         // k tile
    int bh = blockIdx.z;
    int b = bh / HEADS, hd = bh - b * HEADS;
    size_t bq0 = (size_t)b * NTOK;
    float* Cp = g_scores + (size_t)bh * NTOK * NTOK;

    // load Q (hi,lo) and K (hi,lo) tiles
#pragma unroll
    for (int i = 0; i < 16; ++i) {
        int arr = i >> 2;                 // 0 Qh 1 Ql 2 Kh 3 Kl
        int c = tid + (i & 3) * 256;      // 0..1023
        int row = c >> 3, q8 = c & 7;
        const __nv_bfloat16* src = (arr & 1) ? ql : qh;
        size_t go = (arr < 2)
            ? ((bq0 + m0 + row) * QKV3 + hd * 64 + q8 * 8)
            : ((bq0 + n0k + row) * QKV3 + DD + hd * 64 + q8 * 8);
        cp16(sb + arr * 16384 + SW128b(row * 128 + q8 * 16), src + go);
    }
    cp_commit();
    cp_wait<0>();
    __syncthreads();

    int m_warp = (warp >> 2) * 64;      // 0 / 64
    int n_warp = (warp & 3) * 32;       // 0..96

    float acc[4][4][4];
#pragma unroll
    for (int i = 0; i < 4; ++i)
#pragma unroll
        for (int j = 0; j < 4; ++j)
#pragma unroll
            for (int q = 0; q < 4; ++q) acc[i][j][q] = 0.f;

#pragma unroll
    for (int kc = 0; kc < 4; ++kc) {    // K = 64 -> 4 k16 chunks
        uint32_t ah[4][4], al[4][4], bhf[4][2], blf[4][2];
#pragma unroll
        for (int mb = 0; mb < 4; ++mb) {
            int row = m_warp + mb * 16 + (lane & 15);
            uint32_t o = SW128b(row * 128 + (kc * 2 + (lane >> 4)) * 16);
            ldsm_x4(ah[mb], sb + o);
            ldsm_x4(al[mb], sb + 16384 + o);
        }
#pragma unroll
        for (int nb = 0; nb < 4; ++nb) {
            int rown = n_warp + nb * 8 + (lane & 7);
            uint32_t o = SW128b(rown * 128 + (kc * 2 + ((lane >> 3) & 1)) * 16);
            ldsm_x2(bhf[nb], sb + 32768 + o);
            ldsm_x2(blf[nb], sb + 49152 + o);
        }
#pragma unroll
        for (int mb = 0; mb < 4; ++mb)
#pragma unroll
            for (int nb = 0; nb < 4; ++nb) {
                mma_bf16(acc[mb][nb], ah[mb], bhf[nb]);
                mma_bf16(acc[mb][nb], ah[mb], blf[nb]);
                mma_bf16(acc[mb][nb], al[mb], bhf[nb]);
            }
    }

    // store raw S (scale already folded into Q)
#pragma unroll
    for (int mb = 0; mb < 4; ++mb)
#pragma unroll
        for (int nb = 0; nb < 4; ++nb) {
            int r0 = m0 + m_warp + mb * 16 + (lane >> 2);
            int cc = n0k + n_warp + nb * 8 + (lane & 3) * 2;
#pragma unroll
            for (int half = 0; half < 2; ++half) {
                *reinterpret_cast<float2*>(Cp + (size_t)(r0 + half * 8) * NTOK + cc) =
                    make_float2(acc[mb][nb][half * 2], acc[mb][nb][half * 2 + 1]);
            }
        }
}

// -------- attention PV + fused online softmax: O = softmax(S) @ V ----------
// CTA: 128 q-rows x 64 d per (bh). Grid (8, 96). 256 threads.
// Loops over 16 kv-chunks of 64. Smem: Ph,Pl 16KB each; Vh,Vl 8KB each;
// + m/l/alpha stats (3 x 512 B). Each S-row chunk is owned by 16 consecutive
// lanes of one warp (row mod 16 == 2w or 2w+1) -> 16-lane shfl reductions.
#define PV_VOFF   32768
#define PV_STATS  49152
#define PV_SMEM   50688

__global__ void __launch_bounds__(256)
attn_pv_softmax_hmma(const __nv_bfloat16* __restrict__ qh,
                     const __nv_bfloat16* __restrict__ ql,
                     __nv_bfloat16* __restrict__ oh, __nv_bfloat16* __restrict__ ol) {
    extern __shared__ char smem[];
    uint32_t sb = smem_u32(smem);
    int tid = threadIdx.x, warp = tid >> 5, lane = tid & 31;
    int m0 = blockIdx.x * 128;
    int bh = blockIdx.y;
    int b = bh / HEADS, hd = bh - b * HEADS;
    size_t bq0 = (size_t)b * NTOK;
    const float* Sg = g_scores + (size_t)bh * NTOK * NTOK;

    float* mS = reinterpret_cast<float*>(smem + PV_STATS);          // [128]
    float* lS = reinterpret_cast<float*>(smem + PV_STATS + 512);    // [128]
    float* aS = reinterpret_cast<float*>(smem + PV_STATS + 1024);   // [128]
    if (tid < 128) { mS[tid] = -1e30f; lS[tid] = 0.f; }
    __syncthreads();

    int m_warp = (warp >> 2) * 64;
    int n_warp = (warp & 3) * 16;       // d within head: 0,16,32,48

    float acc[4][2][4];
#pragma unroll
    for (int i = 0; i < 4; ++i)
#pragma unroll
        for (int j = 0; j < 2; ++j)
#pragma unroll
            for (int q = 0; q < 4; ++q) acc[i][j][q] = 0.f;

    for (int kt = 0; kt < NTOK / 64; ++kt) {
        // V tile (cp.async; overlaps the S->P softmax/convert below)
#pragma unroll
        for (int i = 0; i < 4; ++i) {
            int arr = i >> 1;             // 0 Vh 1 Vl
            int c = tid + (i & 1) * 256;  // 0..511
            int row = c >> 3, q8 = c & 7;
            const __nv_bfloat16* src = arr ? ql : qh;
            cp16(sb + PV_VOFF + arr * 8192 + SW128b(row * 128 + q8 * 16),
                 src + (bq0 + kt * 64 + row) * QKV3 + 2 * DD + hd * 64 + q8 * 8);
        }
        cp_commit();

        // S chunk: online softmax (16-lane row reduction) -> bf16 hi/lo smem
#pragma unroll
        for (int i = 0; i < 8; ++i) {
            int lin = tid + i * 256;          // float4 index 0..2047
            int row = lin >> 4, c0 = (lin & 15) * 4;
            float4 p = *reinterpret_cast<const float4*>(
                Sg + (size_t)(m0 + row) * NTOK + kt * 64 + c0);
            float cmax = fmaxf(fmaxf(p.x, p.y), fmaxf(p.z, p.w));
#pragma unroll
            for (int o = 1; o <= 8; o <<= 1)
                cmax = fmaxf(cmax, __shfl_xor_sync(0xffffffffu, cmax, o));
            float mold = mS[row];
            float mnew = fmaxf(mold, cmax);
            p.x = __expf(p.x - mnew);
            p.y = __expf(p.y - mnew);
            p.z = __expf(p.z - mnew);
            p.w = __expf(p.w - mnew);
            float ss = p.x + p.y + p.z + p.w;
#pragma unroll
            for (int o = 1; o <= 8; o <<= 1)
                ss += __shfl_xor_sync(0xffffffffu, ss, o);
            if ((lane & 15) == 0) {
                float alpha = __expf(mold - mnew);
                aS[row] = alpha;
                lS[row] = lS[row] * alpha + ss;
                mS[row] = mnew;
            }
            __nv_bfloat16 h0 = __float2bfloat16(p.x), h1 = __float2bfloat16(p.y);
            __nv_bfloat16 h2 = __float2bfloat16(p.z), h3 = __float2bfloat16(p.w);
            uint2 hi2, lo2;
            hi2.x = pack_bf2(h0, h1); hi2.y = pack_bf2(h2, h3);
            lo2.x = pack_bf2(__float2bfloat16(p.x - __bfloat162float(h0)),
                             __float2bfloat16(p.y - __bfloat162float(h1)));
            lo2.y = pack_bf2(__float2bfloat16(p.z - __bfloat162float(h2)),
                             __float2bfloat16(p.w - __bfloat162float(h3)));
            uint32_t o = SW128b(row * 128 + c0 * 2);
            *reinterpret_cast<uint2*>(smem + o) = hi2;
            *reinterpret_cast<uint2*>(smem + 16384 + o) = lo2;
        }
        cp_wait<0>();
        __syncthreads();

        // rescale Oacc by alpha, then accumulate P @ V
#pragma unroll
        for (int mb = 0; mb < 4; ++mb) {
            int rl = m_warp + mb * 16 + (lane >> 2);
            float a0 = aS[rl], a1 = aS[rl + 8];
#pragma unroll
            for (int nb = 0; nb < 2; ++nb) {
                acc[mb][nb][0] *= a0; acc[mb][nb][1] *= a0;
                acc[mb][nb][2] *= a1; acc[mb][nb][3] *= a1;
            }
        }

#pragma unroll
        for (int kc = 0; kc < 4; ++kc) {   // 64 kv -> 4 k16 chunks
            uint32_t ah[4][4], al[4][4], bhf[2][2], blf[2][2];
#pragma unroll
            for (int mb = 0; mb < 4; ++mb) {
                int row = m_warp + mb * 16 + (lane & 15);
                uint32_t o = SW128b(row * 128 + (kc * 2 + (lane >> 4)) * 16);
                ldsm_x4(ah[mb], sb + o);
                ldsm_x4(al[mb], sb + 16384 + o);
            }
#pragma unroll
            for (int nb = 0; nb < 2; ++nb) {
                int vrow = kc * 16 + (lane & 15);
                uint32_t o = SW128b(vrow * 128 + (n_warp + nb * 8) * 2);
                ldsm_x2_t(bhf[nb], sb + PV_VOFF + o);
                ldsm_x2_t(blf[nb], sb + PV_VOFF + 8192 + o);
            }
#pragma unroll
            for (int mb = 0; mb < 4; ++mb)
#pragma unroll
                for (int nb = 0; nb < 2; ++nb) {
                    mma_bf16(acc[mb][nb], ah[mb], bhf[nb]);
                    mma_bf16(acc[mb][nb], ah[mb], blf[nb]);
                    mma_bf16(acc[mb][nb], al[mb], bhf[nb]);
                }
        }
        __syncthreads();
    }

    // epilogue: O / l, split hi/lo, store
#pragma unroll
    for (int mb = 0; mb < 4; ++mb) {
        int rl = m_warp + mb * 16 + (lane >> 2);
        float inv0 = 1.0f / lS[rl], inv1 = 1.0f / lS[rl + 8];
#pragma unroll
        for (int nb = 0; nb < 2; ++nb) {
            int r0 = m0 + rl;
            int cc = hd * 64 + n_warp + nb * 8 + (lane & 3) * 2;
#pragma unroll
            for (int half = 0; half < 2; ++half) {
                size_t idx = (bq0 + r0 + half * 8) * DD + cc;
                float inv = half ? inv1 : inv0;
                float v0 = acc[mb][nb][half * 2] * inv;
                float v1 = acc[mb][nb][half * 2 + 1] * inv;
                __nv_bfloat16 h0 = __float2bfloat16(v0);
                __nv_bfloat16 h1 = __float2bfloat16(v1);
                *reinterpret_cast<uint32_t*>(oh + idx) = pack_bf2(h0, h1);
                *reinterpret_cast<uint32_t*>(ol + idx) =
                    pack_bf2(__float2bfloat16(v0 - __bfloat162float(h0)),
                             __float2bfloat16(v1 - __bfloat162float(h1)));
            }
        }
    }
}

// ------------------------------- launcher ----------------------------------
extern "C" void kernel_launch(void* const* d_in, const int* in_sizes, int n_in,
                              void* d_out, int out_size) {
    const float* x       = (const float*)d_in[0];
    const float* w_conv  = (const float*)d_in[1];
    const float* b_conv  = (const float*)d_in[2];
    const float* pos_emb = (const float*)d_in[3];
    const float* ln1_w   = (const float*)d_in[4];
    const float* ln1_b   = (const float*)d_in[5];
    const float* qkv_w   = (const float*)d_in[6];
    const float* out_w   = (const float*)d_in[7];
    const float* out_b   = (const float*)d_in[8];
    const float* ln2_w   = (const float*)d_in[9];
    const float* ln2_b   = (const float*)d_in[10];
    const float* w1      = (const float*)d_in[11];
    const float* b1      = (const float*)d_in[12];
    const float* w2      = (const float*)d_in[13];
    const float* b2      = (const float*)d_in[14];

    float* h = (float*)d_out;

    __nv_bfloat16 *yh, *yl, *oh, *ol, *mh, *ml, *qsh, *qsl;
    cudaGetSymbolAddress((void**)&yh, g_yh);
    cudaGetSymbolAddress((void**)&yl, g_yl);
    cudaGetSymbolAddress((void**)&oh, g_oh);
    cudaGetSymbolAddress((void**)&ol, g_ol);
    cudaGetSymbolAddress((void**)&mh, g_mh);
    cudaGetSymbolAddress((void**)&ml, g_ml);
    cudaGetSymbolAddress((void**)&qsh, g_qsh);
    cudaGetSymbolAddress((void**)&qsl, g_qsl);

    __nv_bfloat16 *wqh, *wql, *woh, *wol, *w1h, *w1l, *w2h, *w2l;
    cudaGetSymbolAddress((void**)&wqh, g_wq_hi);
    cudaGetSymbolAddress((void**)&wql, g_wq_lo);
    cudaGetSymbolAddress((void**)&woh, g_wo_hi);
    cudaGetSymbolAddress((void**)&wol, g_wo_lo);
    cudaGetSymbolAddress((void**)&w1h, g_w1_hi);
    cudaGetSymbolAddress((void**)&w1l, g_w1_lo);
    cudaGetSymbolAddress((void**)&w2h, g_w2_hi);
    cudaGetSymbolAddress((void**)&w2l, g_w2_lo);

    cudaFuncSetAttribute(mma_gemm<EPI_BIAS_RES>,
                         cudaFuncAttributeMaxDynamicSharedMemorySize, SMEM_BYTES);
    cudaFuncSetAttribute(mma_gemm<EPI_GELU_SPLIT>,
                         cudaFuncAttributeMaxDynamicSharedMemorySize, SMEM_BYTES);
    cudaFuncSetAttribute(mma_gemm<EPI_QKV_SPLIT>,
                         cudaFuncAttributeMaxDynamicSharedMemorySize, SMEM_BYTES);
    cudaFuncSetAttribute(attn_scores_hmma,
                         cudaFuncAttributeMaxDynamicSharedMemorySize, SC_SMEM);
    cudaFuncSetAttribute(attn_pv_softmax_hmma,
                         cudaFuncAttributeMaxDynamicSharedMemorySize, PV_SMEM);

    patch_embed_kernel<<<BN_, 256>>>(x, w_conv, b_conv, pos_emb, h);

    for (int L = 0; L < DEPTH; ++L) {
        wt_convert_kernel<<<dim3(QKV3 / 32, DD / 32), 256>>>(
            qkv_w + (size_t)L * DD * QKV3,
            wqh + (size_t)L * QKV3 * DD, wql + (size_t)L * QKV3 * DD, DD, QKV3);
        wt_convert_kernel<<<dim3(DD / 32, DD / 32), 256>>>(
            out_w + (size_t)L * DD * DD,
            woh + (size_t)L * DD * DD, wol + (size_t)L * DD * DD, DD, DD);
        wt_convert_kernel<<<dim3(MLPD / 32, DD / 32), 256>>>(
            w1 + (size_t)L * DD * MLPD,
            w1h + (size_t)L * MLPD * DD, w1l + (size_t)L * MLPD * DD, DD, MLPD);
        wt_convert_kernel<<<dim3(DD / 32, MLPD / 32), 256>>>(
            w2 + (size_t)L * MLPD * DD,
            w2h + (size_t)L * DD * MLPD, w2l + (size_t)L * DD * MLPD, MLPD, DD);
    }

    for (int L = 0; L < DEPTH; ++L) {
        // --- MHSA ---
        layernorm_split_kernel<<<BN_, 256>>>(h, ln1_w + L * DD, ln1_b + L * DD, yh, yl);

        mma_gemm<EPI_QKV_SPLIT><<<dim3(QKV3 / 128, BN_ / 128), 256, SMEM_BYTES>>>(
            yh, yl, wqh + (size_t)L * QKV3 * DD, wql + (size_t)L * QKV3 * DD,
            nullptr, nullptr, nullptr, qsh, qsl, BN_, QKV3, DD);

        attn_scores_hmma<<<dim3(8, 8, BB * HEADS), 256, SC_SMEM>>>(qsh, qsl);
        attn_pv_softmax_hmma<<<dim3(8, BB * HEADS), 256, PV_SMEM>>>(qsh, qsl, oh, ol);

        mma_gemm<EPI_BIAS_RES><<<dim3(DD / 128, BN_ / 128), 256, SMEM_BYTES>>>(
            oh, ol, woh + (size_t)L * DD * DD, wol + (size_t)L * DD * DD,
            h, out_b + L * DD, h, nullptr, nullptr, BN_, DD, DD);

        // --- FFN ---
        layernorm_split_kernel<<<BN_, 256>>>(h, ln2_w + L * DD, ln2_b + L * DD, yh, yl);

        mma_gemm<EPI_GELU_SPLIT><<<dim3(MLPD / 128, BN_ / 128), 256, SMEM_BYTES>>>(
            yh, yl, w1h + (size_t)L * MLPD * DD, w1l + (size_t)L * MLPD * DD,
            nullptr, b1 + L * MLPD, nullptr, mh, ml, BN_, MLPD, DD);

        mma_gemm<EPI_BIAS_RES><<<dim3(DD / 128, BN_ / 128), 256, SMEM_BYTES>>>(
            mh, ml, w2h + (size_t)L * DD * MLPD, w2l + (size_t)L * DD * MLPD,
            h, b2 + L * DD, h, nullptr, nullptr, BN_, DD, MLPD);
    }
    (void)in_sizes; (void)n_in; (void)out_size;
}